// round 1
// baseline (speedup 1.0000x reference)
#include <cuda_runtime.h>
#include <cuda_bf16.h>
#include <stdint.h>

// Problem constants
#define BATCH     1024
#define NCTX      200
#define D         128
#define F         384      // 3*D
#define OUTD      128
#define TILE_N    64
#define NTILES    4        // ceil(200/64)

// Shared memory layout (bf16 strides padded to avoid bank conflicts)
#define CTX_STRIDE   392   // bf16 elems per row (384 + 8)
#define CTX_WSTRIDE  196   // in b32 words
#define COMB_STRIDE  132   // f32 elems per row

#define OFF_WS    0
#define SZ_WS     (D * CTX_STRIDE * 2)                 // 100352
#define OFF_CTX   (OFF_WS + SZ_WS)                     // 100352
#define SZ_CTX    (TILE_N * CTX_STRIDE * 2)            // 50176
#define OFF_COMB  (OFF_CTX + SZ_CTX)                   // 150528
#define SZ_COMB   (TILE_N * COMB_STRIDE * 4)           // 33792
#define OFF_AV    (OFF_COMB + SZ_COMB)                 // 184320
#define OFF_ESC   (OFF_AV + 512)                       // 184832
#define OFF_CODE  (OFF_ESC + 256)                      // 185088
#define SMEM_BYTES (OFF_CODE + 512)                    // 185600

__device__ __forceinline__ float fast_tanhf(float x) {
    float y;
    asm("tanh.approx.f32 %0, %1;" : "=f"(y) : "f"(x));
    return y;
}

__device__ __forceinline__ void mma16816(float* acc, uint32_t a0, uint32_t a1,
                                         uint32_t a2, uint32_t a3,
                                         uint32_t b0, uint32_t b1) {
    asm volatile(
        "mma.sync.aligned.m16n8k16.row.col.f32.bf16.bf16.f32 "
        "{%0,%1,%2,%3},{%4,%5,%6,%7},{%8,%9},{%0,%1,%2,%3};"
        : "+f"(acc[0]), "+f"(acc[1]), "+f"(acc[2]), "+f"(acc[3])
        : "r"(a0), "r"(a1), "r"(a2), "r"(a3), "r"(b0), "r"(b1));
}

__global__ void __launch_bounds__(256, 1)
acv_fused_kernel(const int* __restrict__ xs_xt,
                 const int* __restrict__ path_idx,
                 const float* __restrict__ value_vocab,
                 const float* __restrict__ path_vocab,
                 const float* __restrict__ W,
                 const float* __restrict__ att_vec,
                 const float* __restrict__ dense_w,
                 const float* __restrict__ dense_b,
                 float* __restrict__ out)
{
    extern __shared__ unsigned char smem[];
    __nv_bfloat16* Ws   = (__nv_bfloat16*)(smem + OFF_WS);
    __nv_bfloat16* ctx  = (__nv_bfloat16*)(smem + OFF_CTX);
    float*         comb = (float*)(smem + OFF_COMB);
    float*         avs  = (float*)(smem + OFF_AV);
    float*         esc  = (float*)(smem + OFF_ESC);
    float*         code_s = (float*)(smem + OFF_CODE);

    const int tid = threadIdx.x;
    const int b   = blockIdx.x;

    // ---- Convert W (fp32 [128][384]) -> Ws bf16 [128][392] (d-major) ----
    for (int i = tid; i < D * (F / 4); i += 256) {   // 128*96 float4 loads
        int d = i / 96, j = i % 96;
        float4 v = ((const float4*)W)[d * 96 + j];
        __nv_bfloat162 lo = __floats2bfloat162_rn(v.x, v.y);
        __nv_bfloat162 hi = __floats2bfloat162_rn(v.z, v.w);
        uint32_t* p = (uint32_t*)&Ws[d * CTX_STRIDE + j * 4];
        p[0] = *(uint32_t*)&lo;
        p[1] = *(uint32_t*)&hi;
    }
    if (tid < D) avs[tid] = att_vec[tid];

    const int lane  = tid & 31;
    const int warp  = tid >> 5;
    const int mwarp = warp & 3;   // 4 warps along n-rows (M)
    const int nwarp = warp >> 2;  // 2 warps along d-cols (N)
    const int g  = lane >> 2;     // groupID
    const int tg = lane & 3;      // thread in group

    const uint32_t* ctxw = (const uint32_t*)ctx;
    const uint32_t* wsw  = (const uint32_t*)Ws;

    // A fragment base word offsets (rows within tile)
    const int rowA = mwarp * 16 + g;
    const int aw0 = rowA * CTX_WSTRIDE + tg;
    const int aw1 = (rowA + 8) * CTX_WSTRIDE + tg;
    // B fragment base word offsets (one per n8 subtile)
    int bw[8];
#pragma unroll
    for (int nn = 0; nn < 8; nn++)
        bw[nn] = (nwarp * 64 + nn * 8 + g) * CTX_WSTRIDE + tg;

    float code_acc = 0.f;   // valid for tid < 128
    float esum     = 0.f;

    for (int t = 0; t < NTILES; t++) {
        const int n0 = t * TILE_N;
        __syncthreads();   // protect ctx/comb reuse from previous iteration

        // ---- Gather: 64 rows x 96 float4 -> bf16 ctx tile ----
        for (int i = tid; i < TILE_N * 96; i += 256) {
            int r = i / 96, q = i % 96;       // q = float4 index within 384
            int seg = q >> 5, j = q & 31;     // seg 0:xs 1:path 2:xt ; j 0..31
            int n = n0 + r;
            uint32_t dstw = (uint32_t)(r * CTX_WSTRIDE + q * 2);
            uint32_t* dp = (uint32_t*)ctx + dstw;
            if (n < NCTX) {
                int src;
                const float4* tab;
                if (seg == 0)      { src = xs_xt[(b * NCTX + n) * 2];     tab = (const float4*)value_vocab; }
                else if (seg == 1) { src = path_idx[b * NCTX + n];        tab = (const float4*)path_vocab; }
                else               { src = xs_xt[(b * NCTX + n) * 2 + 1]; tab = (const float4*)value_vocab; }
                float4 v = tab[(size_t)src * 32 + j];
                __nv_bfloat162 lo = __floats2bfloat162_rn(v.x, v.y);
                __nv_bfloat162 hi = __floats2bfloat162_rn(v.z, v.w);
                dp[0] = *(uint32_t*)&lo;
                dp[1] = *(uint32_t*)&hi;
            } else {
                dp[0] = 0u;
                dp[1] = 0u;
            }
        }
        __syncthreads();

        // ---- GEMM: comb_tile[64][128] = ctx[64][384] @ Ws^T ----
        float acc[8][4];
#pragma unroll
        for (int nn = 0; nn < 8; nn++)
#pragma unroll
            for (int c = 0; c < 4; c++) acc[nn][c] = 0.f;

#pragma unroll
        for (int kk = 0; kk < F / 16; kk++) {     // 24 k-steps
            uint32_t a0 = ctxw[aw0 + kk * 8];
            uint32_t a1 = ctxw[aw1 + kk * 8];
            uint32_t a2 = ctxw[aw0 + kk * 8 + 4];
            uint32_t a3 = ctxw[aw1 + kk * 8 + 4];
#pragma unroll
            for (int nn = 0; nn < 8; nn++) {
                uint32_t b0 = wsw[bw[nn] + kk * 8];
                uint32_t b1 = wsw[bw[nn] + kk * 8 + 4];
                mma16816(acc[nn], a0, a1, a2, a3, b0, b1);
            }
        }

        // ---- comb = tanh(acc) -> smem (fp32) ----
#pragma unroll
        for (int nn = 0; nn < 8; nn++) {
            int col = nwarp * 64 + nn * 8 + tg * 2;
            int r0  = mwarp * 16 + g;
            float2 v0 = make_float2(fast_tanhf(acc[nn][0]), fast_tanhf(acc[nn][1]));
            float2 v1 = make_float2(fast_tanhf(acc[nn][2]), fast_tanhf(acc[nn][3]));
            *(float2*)&comb[r0 * COMB_STRIDE + col]       = v0;
            *(float2*)&comb[(r0 + 8) * COMB_STRIDE + col] = v1;
        }
        __syncthreads();

        // ---- scores + exp (no max-subtraction: |s| <= sum|a| ~ 5, safe) ----
        {
            float4 a4 = *(const float4*)&avs[lane * 4];
#pragma unroll
            for (int rr = 0; rr < 8; rr++) {
                int row = warp * 8 + rr;
                float4 c4 = *(const float4*)&comb[row * COMB_STRIDE + lane * 4];
                float p = c4.x * a4.x + c4.y * a4.y + c4.z * a4.z + c4.w * a4.w;
#pragma unroll
                for (int off = 16; off > 0; off >>= 1)
                    p += __shfl_xor_sync(0xFFFFFFFFu, p, off);
                if (lane == 0)
                    esc[row] = (n0 + row < NCTX) ? __expf(p) : 0.f;
            }
        }
        __syncthreads();

        // ---- streaming weighted accumulation into registers ----
        if (tid < D) {
#pragma unroll 8
            for (int r = 0; r < TILE_N; r++) {
                float e = esc[r];
                esum += e;
                code_acc += e * comb[r * COMB_STRIDE + tid];
            }
        }
    }

    __syncthreads();
    if (tid < D) code_s[tid] = code_acc / esum;
    __syncthreads();

    // ---- out = sigmoid(code @ dense_w + dense_b) ----
    if (tid < OUTD) {
        float z = dense_b[tid];
#pragma unroll 8
        for (int d = 0; d < D; d++)
            z += code_s[d] * dense_w[d * OUTD + tid];
        out[b * OUTD + tid] = 1.f / (1.f + __expf(-z));
    }
}

extern "C" void kernel_launch(void* const* d_in, const int* in_sizes, int n_in,
                              void* d_out, int out_size)
{
    const int*   xs_xt       = (const int*)d_in[0];
    const int*   path_idx    = (const int*)d_in[1];
    const float* value_vocab = (const float*)d_in[2];
    const float* path_vocab  = (const float*)d_in[3];
    const float* W           = (const float*)d_in[4];
    const float* att_vec     = (const float*)d_in[5];
    const float* dense_w     = (const float*)d_in[6];
    const float* dense_b     = (const float*)d_in[7];
    float*       out         = (float*)d_out;

    cudaFuncSetAttribute(acv_fused_kernel,
                         cudaFuncAttributeMaxDynamicSharedMemorySize, SMEM_BYTES);
    acv_fused_kernel<<<BATCH, 256, SMEM_BYTES>>>(
        xs_xt, path_idx, value_vocab, path_vocab, W, att_vec,
        dense_w, dense_b, out);
}

// round 2
// speedup vs baseline: 2.3076x; 2.3076x over previous
#include <cuda_runtime.h>
#include <cuda_bf16.h>
#include <stdint.h>

// Problem constants
#define BATCH     1024
#define NCTX      200
#define D         128
#define F         384      // 3*D
#define OUTD      128
#define TILE_N    32
#define NTILES    7        // 7*32 = 224 >= 200

#define CTX_WSTRIDE  196   // b32 words per ctx row (384 bf16 + 8 pad)
#define COMB_STRIDE  132   // f32 per comb row

// Shared memory layout
#define OFF_WS     0
#define SZ_WS      (D * CTX_WSTRIDE * 4)          // 100352
#define OFF_CTX0   (OFF_WS + SZ_WS)               // 100352
#define SZ_CTXBUF  (TILE_N * CTX_WSTRIDE * 4)     // 25088
#define OFF_CTX1   (OFF_CTX0 + SZ_CTXBUF)         // 125440
#define OFF_COMB   (OFF_CTX1 + SZ_CTXBUF)         // 150528
#define SZ_COMB    (TILE_N * COMB_STRIDE * 4)     // 16896
#define OFF_AV     (OFF_COMB + SZ_COMB)           // 167424
#define OFF_ESC    (OFF_AV + 512)                 // 167936
#define OFF_IDX    (OFF_ESC + 256)                // 168192 (3*224*4 = 2688)
#define OFF_CODE2  (OFF_IDX + 2688)               // 170880
#define OFF_ZSC    (OFF_CODE2 + 512)              // 171392
#define OFF_MISC   (OFF_ZSC + 512)                // 171904
#define SMEM_BYTES (OFF_MISC + 64)                // 171968

// W converted to bf16 once per launch (prep kernel)
__device__ uint32_t g_Wbf[D * CTX_WSTRIDE];

__global__ void prep_w_kernel(const float* __restrict__ W) {
    int i = blockIdx.x * 256 + threadIdx.x;      // 0 .. 12287 (128*96 float4)
    int d = i / 96, j = i % 96;
    float4 v = ((const float4*)W)[i];
    __nv_bfloat162 lo = __floats2bfloat162_rn(v.x, v.y);
    __nv_bfloat162 hi = __floats2bfloat162_rn(v.z, v.w);
    g_Wbf[d * CTX_WSTRIDE + j * 2]     = *(uint32_t*)&lo;
    g_Wbf[d * CTX_WSTRIDE + j * 2 + 1] = *(uint32_t*)&hi;
}

__device__ __forceinline__ float fast_tanhf(float x) {
    float y;
    asm("tanh.approx.f32 %0, %1;" : "=f"(y) : "f"(x));
    return y;
}

__device__ __forceinline__ void mma16816(float* acc, uint32_t a0, uint32_t a1,
                                         uint32_t a2, uint32_t a3,
                                         uint32_t b0, uint32_t b1) {
    asm volatile(
        "mma.sync.aligned.m16n8k16.row.col.f32.bf16.bf16.f32 "
        "{%0,%1,%2,%3},{%4,%5,%6,%7},{%8,%9},{%0,%1,%2,%3};"
        : "+f"(acc[0]), "+f"(acc[1]), "+f"(acc[2]), "+f"(acc[3])
        : "r"(a0), "r"(a1), "r"(a2), "r"(a3), "r"(b0), "r"(b1));
}

__device__ __forceinline__ float4 ldg_nc_v4(const float* p) {
    float4 r;
    asm volatile("ld.global.nc.v4.f32 {%0,%1,%2,%3}, [%4];"
                 : "=f"(r.x), "=f"(r.y), "=f"(r.z), "=f"(r.w) : "l"(p));
    return r;
}

__global__ void __launch_bounds__(256, 1)
acv_fused_kernel(const int* __restrict__ xs_xt,
                 const int* __restrict__ path_idx,
                 const float* __restrict__ value_vocab,
                 const float* __restrict__ path_vocab,
                 const float* __restrict__ att_vec,
                 const float* __restrict__ dense_w,
                 const float* __restrict__ dense_b,
                 float* __restrict__ out)
{
    extern __shared__ unsigned char smem[];
    float* comb   = (float*)(smem + OFF_COMB);
    float* avs    = (float*)(smem + OFF_AV);
    float* esc    = (float*)(smem + OFF_ESC);
    int*   sxi    = (int*)(smem + OFF_IDX);
    int*   pxi    = sxi + 224;
    int*   txi    = pxi + 224;
    float* code2  = (float*)(smem + OFF_CODE2);
    float* zsc    = (float*)(smem + OFF_ZSC);
    float* misc   = (float*)(smem + OFF_MISC);

    const int tid = threadIdx.x;
    const int b   = blockIdx.x;

    // ---- cp.async W (bf16, pre-converted) into smem, overlapped with idx load ----
    {
        uint32_t ws_s = (uint32_t)__cvta_generic_to_shared(smem + OFF_WS);
        const char* wg = (const char*)g_Wbf;
        for (int i = tid; i < SZ_WS / 16; i += 256) {
            asm volatile("cp.async.cg.shared.global [%0], [%1], 16;"
                         :: "r"(ws_s + i * 16), "l"(wg + i * 16));
        }
        asm volatile("cp.async.commit_group;");
    }

    // ---- stage all indices for this batch in smem ----
    for (int i = tid; i < 2 * NCTX; i += 256) {
        int v = xs_xt[b * 2 * NCTX + i];
        if (i & 1) txi[i >> 1] = v; else sxi[i >> 1] = v;
    }
    for (int i = tid; i < NCTX; i += 256) pxi[i] = path_idx[b * NCTX + i];
    if (tid < 24) { sxi[NCTX + tid] = 0; pxi[NCTX + tid] = 0; txi[NCTX + tid] = 0; }
    if (tid < D) avs[tid] = att_vec[tid];
    __syncthreads();

    const int lane  = tid & 31;
    const int warp  = tid >> 5;
    const int mwarp = warp & 1;   // 2 warps along 32 rows
    const int nwarp = warp >> 1;  // 4 warps along 128 cols
    const int g  = lane >> 2;
    const int tg = lane & 3;

    const uint32_t* wsw = (const uint32_t*)(smem + OFF_WS);
    const int rowA = mwarp * 16 + g;
    const int aw0 = rowA * CTX_WSTRIDE + tg;
    const int aw1 = (rowA + 8) * CTX_WSTRIDE + tg;
    int bw[4];
#pragma unroll
    for (int nn = 0; nn < 4; nn++)
        bw[nn] = (nwarp * 32 + nn * 8 + g) * CTX_WSTRIDE + tg;

    // ---- gather helper data (per-thread static mapping) ----
    int g_r[12], g_q[12];
#pragma unroll
    for (int s = 0; s < 12; s++) {
        int i = tid + s * 256;
        g_r[s] = i / 96;
        g_q[s] = i % 96;
    }

    // ---- pre-loop: gather tile 0 ----
    float4 gp[12];
#pragma unroll
    for (int s = 0; s < 12; s++) {
        int q = g_q[s], seg = q >> 5, j = q & 31;
        int n = g_r[s];
        int idx = (seg == 0) ? sxi[n] : (seg == 1) ? pxi[n] : txi[n];
        const float* tab = (seg == 1) ? path_vocab : value_vocab;
        gp[s] = ldg_nc_v4(tab + (size_t)idx * 128 + j * 4);
    }
#pragma unroll
    for (int s = 0; s < 12; s++) {
        __nv_bfloat162 lo = __floats2bfloat162_rn(gp[s].x, gp[s].y);
        __nv_bfloat162 hi = __floats2bfloat162_rn(gp[s].z, gp[s].w);
        uint32_t* dp = (uint32_t*)(smem + OFF_CTX0) + g_r[s] * CTX_WSTRIDE + g_q[s] * 2;
        dp[0] = *(uint32_t*)&lo;
        dp[1] = *(uint32_t*)&hi;
    }
    asm volatile("cp.async.wait_group 0;");
    __syncthreads();

    float code_acc = 0.f;
    float esum     = 0.f;
    const int half = tid >> 7;      // 0/1: row-halves for accumulation
    const int dcol = tid & 127;

    for (int t = 0; t < NTILES; t++) {
        // ---- prefetch gather for tile t+1 (loads in flight during GEMM) ----
        if (t < NTILES - 1) {
            const int n0 = (t + 1) * TILE_N;
#pragma unroll
            for (int s = 0; s < 12; s++) {
                int q = g_q[s], seg = q >> 5, j = q & 31;
                int n = n0 + g_r[s];
                int idx = (seg == 0) ? sxi[n] : (seg == 1) ? pxi[n] : txi[n];
                const float* tab = (seg == 1) ? path_vocab : value_vocab;
                gp[s] = ldg_nc_v4(tab + (size_t)idx * 128 + j * 4);
            }
        }

        // ---- GEMM: comb_tile[32][128] = ctx[32][384] @ Ws^T ----
        const uint32_t* cw = (const uint32_t*)(smem + OFF_CTX0 + (t & 1) * SZ_CTXBUF);
        float acc[4][4];
#pragma unroll
        for (int nn = 0; nn < 4; nn++)
#pragma unroll
            for (int c = 0; c < 4; c++) acc[nn][c] = 0.f;

#pragma unroll
        for (int kk = 0; kk < F / 16; kk++) {
            uint32_t a0 = cw[aw0 + kk * 8];
            uint32_t a1 = cw[aw1 + kk * 8];
            uint32_t a2 = cw[aw0 + kk * 8 + 4];
            uint32_t a3 = cw[aw1 + kk * 8 + 4];
#pragma unroll
            for (int nn = 0; nn < 4; nn++) {
                uint32_t b0 = wsw[bw[nn] + kk * 8];
                uint32_t b1 = wsw[bw[nn] + kk * 8 + 4];
                mma16816(acc[nn], a0, a1, a2, a3, b0, b1);
            }
        }

        // ---- tanh -> comb (fp32 smem) ----
#pragma unroll
        for (int nn = 0; nn < 4; nn++) {
            int col = nwarp * 32 + nn * 8 + tg * 2;
            int r0  = mwarp * 16 + g;
            float2 v0 = make_float2(fast_tanhf(acc[nn][0]), fast_tanhf(acc[nn][1]));
            float2 v1 = make_float2(fast_tanhf(acc[nn][2]), fast_tanhf(acc[nn][3]));
            *(float2*)&comb[r0 * COMB_STRIDE + col]       = v0;
            *(float2*)&comb[(r0 + 8) * COMB_STRIDE + col] = v1;
        }
        __syncthreads();

        // ---- scores + exp (bounded: |s| <= sum|a|, no max needed) ----
        {
            float4 a4 = *(const float4*)&avs[lane * 4];
            const int n0 = t * TILE_N;
#pragma unroll
            for (int rr = 0; rr < 4; rr++) {
                int row = warp * 4 + rr;
                float4 c4 = *(const float4*)&comb[row * COMB_STRIDE + lane * 4];
                float p = c4.x * a4.x + c4.y * a4.y + c4.z * a4.z + c4.w * a4.w;
#pragma unroll
                for (int off = 16; off > 0; off >>= 1)
                    p += __shfl_xor_sync(0xFFFFFFFFu, p, off);
                if (lane == 0)
                    esc[row] = (n0 + row < NCTX) ? __expf(p) : 0.f;
            }
        }
        __syncthreads();

        // ---- streaming weighted accumulation (all 256 threads) ----
#pragma unroll
        for (int r2 = 0; r2 < 16; r2++) {
            int rr = half * 16 + r2;
            float e = esc[rr];
            esum += e;
            code_acc += e * comb[rr * COMB_STRIDE + dcol];
        }

        // ---- store prefetched tile t+1 into the other ctx buffer ----
        if (t < NTILES - 1) {
            uint32_t* buf = (uint32_t*)(smem + OFF_CTX0 + ((t + 1) & 1) * SZ_CTXBUF);
#pragma unroll
            for (int s = 0; s < 12; s++) {
                __nv_bfloat162 lo = __floats2bfloat162_rn(gp[s].x, gp[s].y);
                __nv_bfloat162 hi = __floats2bfloat162_rn(gp[s].z, gp[s].w);
                uint32_t* dp = buf + g_r[s] * CTX_WSTRIDE + g_q[s] * 2;
                dp[0] = *(uint32_t*)&lo;
                dp[1] = *(uint32_t*)&hi;
            }
        }
        __syncthreads();
    }

    // ---- combine halves, normalize ----
    if (half == 1) {
        code2[dcol] = code_acc;
        if (tid == 128) misc[0] = esum;
    }
    __syncthreads();
    if (half == 0) {
        float cs = (code_acc + code2[dcol]) / (esum + misc[0]);
        code2[dcol] = cs;     // reuse as code_s
    }
    __syncthreads();

    // ---- out = sigmoid(code @ dense_w + dense_b), split over d-halves ----
    {
        float z = 0.f;
#pragma unroll 8
        for (int d2 = 0; d2 < 64; d2++) {
            int d = half * 64 + d2;
            z += code2[d] * dense_w[d * OUTD + dcol];
        }
        if (half == 1) zsc[dcol] = z;
        __syncthreads();
        if (half == 0) {
            float zz = z + zsc[dcol] + dense_b[dcol];
            out[b * OUTD + dcol] = 1.f / (1.f + __expf(-zz));
        }
    }
}

extern "C" void kernel_launch(void* const* d_in, const int* in_sizes, int n_in,
                              void* d_out, int out_size)
{
    const int*   xs_xt       = (const int*)d_in[0];
    const int*   path_idx    = (const int*)d_in[1];
    const float* value_vocab = (const float*)d_in[2];
    const float* path_vocab  = (const float*)d_in[3];
    const float* W           = (const float*)d_in[4];
    const float* att_vec     = (const float*)d_in[5];
    const float* dense_w     = (const float*)d_in[6];
    const float* dense_b     = (const float*)d_in[7];
    float*       out         = (float*)d_out;

    prep_w_kernel<<<48, 256>>>(W);

    cudaFuncSetAttribute(acv_fused_kernel,
                         cudaFuncAttributeMaxDynamicSharedMemorySize, SMEM_BYTES);
    acv_fused_kernel<<<BATCH, 256, SMEM_BYTES>>>(
        xs_xt, path_idx, value_vocab, path_vocab, att_vec,
        dense_w, dense_b, out);
}

// round 3
// speedup vs baseline: 2.4779x; 1.0738x over previous
#include <cuda_runtime.h>
#include <cuda_bf16.h>
#include <stdint.h>

// Problem constants
#define BATCH     1024
#define NCTX      200
#define D         128
#define F         384      // 3*D
#define OUTD      128
#define TILE_N    32
#define NTILES    7        // 7*32 = 224 >= 200
#define THREADS   512

#define CTX_WSTRIDE  196   // b32 words per ctx row (384 bf16 + 8 pad) = 784 bytes
#define CTX_BSTRIDE  784
#define COMB_STRIDE  132   // f32 per comb row

// Shared memory layout
#define OFF_WS     0
#define SZ_WS      (D * CTX_BSTRIDE)              // 100352
#define OFF_CTX0   (OFF_WS + SZ_WS)               // 100352
#define SZ_CTXBUF  (TILE_N * CTX_BSTRIDE)         // 25088
#define OFF_CTX1   (OFF_CTX0 + SZ_CTXBUF)         // 125440
#define OFF_COMB   (OFF_CTX1 + SZ_CTXBUF)         // 150528
#define SZ_COMB    (TILE_N * COMB_STRIDE * 4)     // 16896
#define OFF_AV     (OFF_COMB + SZ_COMB)           // 167424
#define OFF_ESC    (OFF_AV + 512)                 // 167936
#define OFF_IDX    (OFF_ESC + 256)                // 168192 (3*224*4 = 2688)
#define OFF_CODE4  (OFF_IDX + 2688)               // 170880 (4*128*4 = 2048)
#define OFF_ESUMS  (OFF_CODE4 + 2048)             // 172928 (16)
#define OFF_ZS     (OFF_ESUMS + 64)               // 172992 (3*128*4 = 1536)
#define SMEM_BYTES (OFF_ZS + 1536)                // 174528

// W converted to bf16 once per launch (prep kernel)
__device__ uint32_t g_Wbf[D * CTX_WSTRIDE];

__global__ void prep_w_kernel(const float* __restrict__ W) {
    int i = blockIdx.x * 256 + threadIdx.x;      // 0 .. 12287 (128*96 float4)
    int d = i / 96, j = i % 96;
    float4 v = ((const float4*)W)[i];
    __nv_bfloat162 lo = __floats2bfloat162_rn(v.x, v.y);
    __nv_bfloat162 hi = __floats2bfloat162_rn(v.z, v.w);
    g_Wbf[d * CTX_WSTRIDE + j * 2]     = *(uint32_t*)&lo;
    g_Wbf[d * CTX_WSTRIDE + j * 2 + 1] = *(uint32_t*)&hi;
}

__device__ __forceinline__ float fast_tanhf(float x) {
    float y;
    asm("tanh.approx.f32 %0, %1;" : "=f"(y) : "f"(x));
    return y;
}

__device__ __forceinline__ void mma16816(float* acc, uint32_t a0, uint32_t a1,
                                         uint32_t a2, uint32_t a3,
                                         uint32_t b0, uint32_t b1) {
    asm volatile(
        "mma.sync.aligned.m16n8k16.row.col.f32.bf16.bf16.f32 "
        "{%0,%1,%2,%3},{%4,%5,%6,%7},{%8,%9},{%0,%1,%2,%3};"
        : "+f"(acc[0]), "+f"(acc[1]), "+f"(acc[2]), "+f"(acc[3])
        : "r"(a0), "r"(a1), "r"(a2), "r"(a3), "r"(b0), "r"(b1));
}

__device__ __forceinline__ void ldsm_x4(uint32_t& r0, uint32_t& r1,
                                        uint32_t& r2, uint32_t& r3,
                                        uint32_t saddr) {
    asm volatile("ldmatrix.sync.aligned.m8n8.x4.shared.b16 {%0,%1,%2,%3}, [%4];"
                 : "=r"(r0), "=r"(r1), "=r"(r2), "=r"(r3) : "r"(saddr));
}

__device__ __forceinline__ float4 ldg_nc_v4(const float* p) {
    float4 r;
    asm volatile("ld.global.nc.v4.f32 {%0,%1,%2,%3}, [%4];"
                 : "=f"(r.x), "=f"(r.y), "=f"(r.z), "=f"(r.w) : "l"(p));
    return r;
}

__global__ void __launch_bounds__(THREADS, 1)
acv_fused_kernel(const int* __restrict__ xs_xt,
                 const int* __restrict__ path_idx,
                 const float* __restrict__ value_vocab,
                 const float* __restrict__ path_vocab,
                 const float* __restrict__ att_vec,
                 const float* __restrict__ dense_w,
                 const float* __restrict__ dense_b,
                 float* __restrict__ out)
{
    extern __shared__ unsigned char smem[];
    float* comb   = (float*)(smem + OFF_COMB);
    float* avs    = (float*)(smem + OFF_AV);
    float* esc    = (float*)(smem + OFF_ESC);
    int*   sxi    = (int*)(smem + OFF_IDX);
    int*   pxi    = sxi + 224;
    int*   txi    = pxi + 224;
    float* code4  = (float*)(smem + OFF_CODE4);
    float* esums  = (float*)(smem + OFF_ESUMS);
    float* zs     = (float*)(smem + OFF_ZS);

    const int tid = threadIdx.x;
    const int b   = blockIdx.x;

    // ---- cp.async W (bf16, pre-converted) into smem, overlapped with idx load ----
    {
        uint32_t ws_s = (uint32_t)__cvta_generic_to_shared(smem + OFF_WS);
        const char* wg = (const char*)g_Wbf;
        for (int i = tid; i < SZ_WS / 16; i += THREADS) {
            asm volatile("cp.async.cg.shared.global [%0], [%1], 16;"
                         :: "r"(ws_s + i * 16), "l"(wg + i * 16));
        }
        asm volatile("cp.async.commit_group;");
    }

    // ---- stage all indices for this batch in smem ----
    for (int i = tid; i < 2 * NCTX; i += THREADS) {
        int v = xs_xt[b * 2 * NCTX + i];
        if (i & 1) txi[i >> 1] = v; else sxi[i >> 1] = v;
    }
    if (tid < NCTX) pxi[tid] = path_idx[b * NCTX + tid];
    if (tid < 24) { sxi[NCTX + tid] = 0; pxi[NCTX + tid] = 0; txi[NCTX + tid] = 0; }
    if (tid < D) avs[tid] = att_vec[tid];
    __syncthreads();

    const int lane  = tid & 31;
    const int warp  = tid >> 5;
    const int mwarp = warp & 1;    // 2 warps along 32 rows
    const int nwarp = warp >> 1;   // 8 warps along 128 cols (16 cols each)
    const int g  = lane >> 2;
    const int tg = lane & 3;

    // ldmatrix per-lane address offsets
    // A: 16x16 bf16 tile (rows m, k): lanes 0-15 -> rows 0-15 @k0; 16-31 -> rows @k+8
    const int a_row = mwarp * 16 + (lane & 15);
    const uint32_t a_off = (uint32_t)(a_row * CTX_BSTRIDE + (lane >> 4) * 16);
    const uint32_t ctx0_s = (uint32_t)__cvta_generic_to_shared(smem + OFF_CTX0);
    const uint32_t ctx1_s = (uint32_t)__cvta_generic_to_shared(smem + OFF_CTX1);
    // B: 16 cols x k16: lanes 0-7 cols n0-7 @k0; 8-15 cols n0-7 @k8; 16-23 n8-15 @k0; 24-31 n8-15 @k8
    const int b_col = nwarp * 16 + ((lane >> 4) << 3) + (lane & 7);
    const uint32_t b_addr0 = (uint32_t)__cvta_generic_to_shared(smem + OFF_WS)
                           + (uint32_t)(b_col * CTX_BSTRIDE + ((lane >> 3) & 1) * 16);

    // ---- gather mapping: 32 rows x 96 quads = 3072 / 512 threads = 6 each ----
    int g_r[6], g_q[6];
#pragma unroll
    for (int s = 0; s < 6; s++) {
        int i = tid + s * THREADS;
        g_r[s] = i / 96;
        g_q[s] = i % 96;
    }

    // ---- pre-loop: gather tile 0 ----
    float4 gp[6];
#pragma unroll
    for (int s = 0; s < 6; s++) {
        int q = g_q[s], seg = q >> 5, j = q & 31;
        int n = g_r[s];
        int idx = (seg == 0) ? sxi[n] : (seg == 1) ? pxi[n] : txi[n];
        const float* tab = (seg == 1) ? path_vocab : value_vocab;
        gp[s] = ldg_nc_v4(tab + (size_t)idx * 128 + j * 4);
    }
#pragma unroll
    for (int s = 0; s < 6; s++) {
        __nv_bfloat162 lo = __floats2bfloat162_rn(gp[s].x, gp[s].y);
        __nv_bfloat162 hi = __floats2bfloat162_rn(gp[s].z, gp[s].w);
        uint32_t* dp = (uint32_t*)(smem + OFF_CTX0) + g_r[s] * CTX_WSTRIDE + g_q[s] * 2;
        dp[0] = *(uint32_t*)&lo;
        dp[1] = *(uint32_t*)&hi;
    }
    asm volatile("cp.async.wait_group 0;");
    __syncthreads();

    float code_acc = 0.f;
    float esum     = 0.f;
    const int grp  = tid >> 7;      // 0..3: 8-row groups for accumulation
    const int dcol = tid & 127;

    for (int t = 0; t < NTILES; t++) {
        // ---- prefetch gather for tile t+1 ----
        if (t < NTILES - 1) {
            const int n0 = (t + 1) * TILE_N;
#pragma unroll
            for (int s = 0; s < 6; s++) {
                int q = g_q[s], seg = q >> 5, j = q & 31;
                int n = n0 + g_r[s];
                int idx = (seg == 0) ? sxi[n] : (seg == 1) ? pxi[n] : txi[n];
                const float* tab = (seg == 1) ? path_vocab : value_vocab;
                gp[s] = ldg_nc_v4(tab + (size_t)idx * 128 + j * 4);
            }
        }

        // ---- GEMM: comb_tile[32][128] = ctx[32][384] @ Ws^T via ldmatrix+mma ----
        const uint32_t a_base = ((t & 1) ? ctx1_s : ctx0_s) + a_off;
        float acc0[4] = {0.f, 0.f, 0.f, 0.f};
        float acc1[4] = {0.f, 0.f, 0.f, 0.f};

#pragma unroll
        for (int kk = 0; kk < F / 16; kk++) {
            uint32_t a0, a1, a2, a3, b0, b1, b2, b3;
            ldsm_x4(a0, a1, a2, a3, a_base + kk * 32);
            ldsm_x4(b0, b1, b2, b3, b_addr0 + kk * 32);
            mma16816(acc0, a0, a1, a2, a3, b0, b1);
            mma16816(acc1, a0, a1, a2, a3, b2, b3);
        }

        // ---- tanh -> comb (fp32 smem) ----
        {
            int r0  = mwarp * 16 + g;
            int c0  = nwarp * 16 + tg * 2;
            float2 v;
            v = make_float2(fast_tanhf(acc0[0]), fast_tanhf(acc0[1]));
            *(float2*)&comb[r0 * COMB_STRIDE + c0] = v;
            v = make_float2(fast_tanhf(acc0[2]), fast_tanhf(acc0[3]));
            *(float2*)&comb[(r0 + 8) * COMB_STRIDE + c0] = v;
            v = make_float2(fast_tanhf(acc1[0]), fast_tanhf(acc1[1]));
            *(float2*)&comb[r0 * COMB_STRIDE + c0 + 8] = v;
            v = make_float2(fast_tanhf(acc1[2]), fast_tanhf(acc1[3]));
            *(float2*)&comb[(r0 + 8) * COMB_STRIDE + c0 + 8] = v;
        }
        __syncthreads();

        // ---- scores + exp (bounded scores: no max-subtraction needed) ----
        {
            float4 a4 = *(const float4*)&avs[lane * 4];
            const int n0 = t * TILE_N;
#pragma unroll
            for (int rr = 0; rr < 2; rr++) {
                int row = warp * 2 + rr;
                float4 c4 = *(const float4*)&comb[row * COMB_STRIDE + lane * 4];
                float p = c4.x * a4.x + c4.y * a4.y + c4.z * a4.z + c4.w * a4.w;
#pragma unroll
                for (int off = 16; off > 0; off >>= 1)
                    p += __shfl_xor_sync(0xFFFFFFFFu, p, off);
                if (lane == 0)
                    esc[row] = (n0 + row < NCTX) ? __expf(p) : 0.f;
            }
        }
        __syncthreads();

        // ---- streaming weighted accumulation (all 512 threads, 8 rows each grp) ----
#pragma unroll
        for (int r2 = 0; r2 < 8; r2++) {
            int rr = grp * 8 + r2;
            float e = esc[rr];
            esum += e;
            code_acc += e * comb[rr * COMB_STRIDE + dcol];
        }

        // ---- store prefetched tile t+1 into the other ctx buffer ----
        if (t < NTILES - 1) {
            uint32_t* buf = (uint32_t*)(smem + OFF_CTX0 + ((t + 1) & 1) * SZ_CTXBUF);
#pragma unroll
            for (int s = 0; s < 6; s++) {
                __nv_bfloat162 lo = __floats2bfloat162_rn(gp[s].x, gp[s].y);
                __nv_bfloat162 hi = __floats2bfloat162_rn(gp[s].z, gp[s].w);
                uint32_t* dp = buf + g_r[s] * CTX_WSTRIDE + g_q[s] * 2;
                dp[0] = *(uint32_t*)&lo;
                dp[1] = *(uint32_t*)&hi;
            }
        }
        __syncthreads();
    }

    // ---- combine 4 group partials, normalize code ----
    if (grp != 0) code4[grp * 128 + dcol] = code_acc;
    if (dcol == 0) esums[grp] = esum;
    __syncthreads();
    if (grp == 0) {
        float tot = esums[0] + esums[1] + esums[2] + esums[3];
        float cs = (code_acc + code4[128 + dcol] + code4[256 + dcol] + code4[384 + dcol]) / tot;
        code4[dcol] = cs;
    }
    __syncthreads();

    // ---- out = sigmoid(code @ dense_w + dense_b), split over 4 d-chunks ----
    {
        float z = 0.f;
#pragma unroll 8
        for (int d2 = 0; d2 < 32; d2++) {
            int d = grp * 32 + d2;
            z += code4[d] * dense_w[d * OUTD + dcol];
        }
        if (grp != 0) zs[(grp - 1) * 128 + dcol] = z;
        __syncthreads();
        if (grp == 0) {
            float zz = z + zs[dcol] + zs[128 + dcol] + zs[256 + dcol] + dense_b[dcol];
            out[b * OUTD + dcol] = 1.f / (1.f + __expf(-zz));
        }
    }
}

extern "C" void kernel_launch(void* const* d_in, const int* in_sizes, int n_in,
                              void* d_out, int out_size)
{
    const int*   xs_xt       = (const int*)d_in[0];
    const int*   path_idx    = (const int*)d_in[1];
    const float* value_vocab = (const float*)d_in[2];
    const float* path_vocab  = (const float*)d_in[3];
    const float* W           = (const float*)d_in[4];
    const float* att_vec     = (const float*)d_in[5];
    const float* dense_w     = (const float*)d_in[6];
    const float* dense_b     = (const float*)d_in[7];
    float*       out         = (float*)d_out;

    prep_w_kernel<<<48, 256>>>(W);

    cudaFuncSetAttribute(acv_fused_kernel,
                         cudaFuncAttributeMaxDynamicSharedMemorySize, SMEM_BYTES);
    acv_fused_kernel<<<BATCH, THREADS, SMEM_BYTES>>>(
        xs_xt, path_idx, value_vocab, path_vocab, att_vec,
        dense_w, dense_b, out);
}

// round 5
// speedup vs baseline: 2.8384x; 1.1455x over previous
#include <cuda_runtime.h>
#include <cuda_bf16.h>
#include <stdint.h>

// Problem constants
#define NCTX      200
#define D         128
#define F         384
#define OUTD      128
#define THREADS   512
#define TILE_N    128
#define NTILES    2            // 2 x 128 = 256 rows (padded, invalid rows idx=0, esc=0)

#define CTX_BSTRIDE  784       // bytes per ctx/W row (384 bf16 + 16B pad)
#define CTX_WSTRIDE  196       // words

// ---- smem layout (bytes) ----
#define OFF_W      0
#define SZ_W       (D * CTX_BSTRIDE)              // 100352
#define OFF_CTX    (OFF_W + SZ_W)                 // 100352
#define SZ_CTX     (TILE_N * CTX_BSTRIDE)         // 100352
#define OFF_IDX    (OFF_CTX + SZ_CTX)             // 200704 : 3*256*4 = 3072
#define OFF_AV     (OFF_IDX + 3072)               // 512
#define OFF_SP     (OFF_AV + 512)                 // 128*4*4 = 2048
#define OFF_ESC    (OFF_SP + 2048)                // 512
#define OFF_CODEP  (OFF_ESC + 512)                // 128*4*4 = 2048
#define OFF_CODES  (OFF_CODEP + 2048)             // 512
#define OFF_ZS     (OFF_CODES + 512)              // 1536
#define OFF_EP     (OFF_ZS + 1536)                // 64
#define SMEM_BYTES (OFF_EP + 64)                  // ~209 KB

// W pre-converted to bf16 with 196-word row stride
__device__ __align__(16) uint32_t g_Wbf[D * CTX_WSTRIDE];

__global__ void prep_w_kernel(const float* __restrict__ W) {
    int i = blockIdx.x * 256 + threadIdx.x;      // 0..12287 (128 rows x 96 quads)
    int d = i / 96, j = i % 96;
    float4 v = ((const float4*)W)[i];
    __nv_bfloat162 lo = __floats2bfloat162_rn(v.x, v.y);
    __nv_bfloat162 hi = __floats2bfloat162_rn(v.z, v.w);
    g_Wbf[d * CTX_WSTRIDE + j * 2]     = *(uint32_t*)&lo;
    g_Wbf[d * CTX_WSTRIDE + j * 2 + 1] = *(uint32_t*)&hi;
}

__device__ __forceinline__ float fast_tanhf(float x) {
    float y; asm("tanh.approx.f32 %0, %1;" : "=f"(y) : "f"(x)); return y;
}
__device__ __forceinline__ void mma16816(float* acc, uint32_t a0, uint32_t a1,
                                         uint32_t a2, uint32_t a3,
                                         uint32_t b0, uint32_t b1) {
    asm volatile(
        "mma.sync.aligned.m16n8k16.row.col.f32.bf16.bf16.f32 "
        "{%0,%1,%2,%3},{%4,%5,%6,%7},{%8,%9},{%0,%1,%2,%3};"
        : "+f"(acc[0]), "+f"(acc[1]), "+f"(acc[2]), "+f"(acc[3])
        : "r"(a0), "r"(a1), "r"(a2), "r"(a3), "r"(b0), "r"(b1));
}
__device__ __forceinline__ void ldsm_x4(uint32_t& r0, uint32_t& r1,
                                        uint32_t& r2, uint32_t& r3, uint32_t saddr) {
    asm volatile("ldmatrix.sync.aligned.m8n8.x4.shared.b16 {%0,%1,%2,%3}, [%4];"
                 : "=r"(r0), "=r"(r1), "=r"(r2), "=r"(r3) : "r"(saddr));
}
__device__ __forceinline__ float4 ldg_nc_v4(const float* p) {
    float4 r;
    asm volatile("ld.global.nc.v4.f32 {%0,%1,%2,%3}, [%4];"
                 : "=f"(r.x), "=f"(r.y), "=f"(r.z), "=f"(r.w) : "l"(p));
    return r;
}

// gather one 128-row tile into ctx (rows n0..n0+127 of padded index arrays)
__device__ __forceinline__ void gather_tile(unsigned char* smem, const int* sxi,
                                            const int* pxi, const int* txi,
                                            const float* value_vocab,
                                            const float* path_vocab,
                                            int n0, int tid)
{
    for (int s = 0; s < 24; s += 4) {
        float4 v[4]; int soff[4];
#pragma unroll
        for (int u = 0; u < 4; u++) {
            int i = tid + (s + u) * THREADS;
            int r = i / 96, q = i - r * 96;
            int seg = q >> 5, j = q & 31;
            int idx = (seg == 0) ? sxi[n0 + r] : (seg == 1) ? pxi[n0 + r] : txi[n0 + r];
            const float* tab = (seg == 1) ? path_vocab : value_vocab;
            v[u] = ldg_nc_v4(tab + (size_t)idx * 128 + j * 4);
            soff[u] = r * CTX_BSTRIDE + q * 8;
        }
#pragma unroll
        for (int u = 0; u < 4; u++) {
            __nv_bfloat162 lo = __floats2bfloat162_rn(v[u].x, v[u].y);
            __nv_bfloat162 hi = __floats2bfloat162_rn(v[u].z, v[u].w);
            uint2 w; w.x = *(uint32_t*)&lo; w.y = *(uint32_t*)&hi;
            *(uint2*)(smem + OFF_CTX + soff[u]) = w;
        }
    }
}

__global__ void __launch_bounds__(THREADS, 1)
acv_fused_kernel(const int* __restrict__ xs_xt,
                 const int* __restrict__ path_idx,
                 const float* __restrict__ value_vocab,
                 const float* __restrict__ path_vocab,
                 const float* __restrict__ att_vec,
                 const float* __restrict__ dense_w,
                 const float* __restrict__ dense_b,
                 float* __restrict__ out)
{
    extern __shared__ unsigned char smem[];
    int*   sxi   = (int*)(smem + OFF_IDX);
    int*   pxi   = sxi + 256;
    int*   txi   = pxi + 256;
    float* avs   = (float*)(smem + OFF_AV);
    float* sp    = (float*)(smem + OFF_SP);
    float* esc   = (float*)(smem + OFF_ESC);
    float* codep = (float*)(smem + OFF_CODEP);
    float* codes = (float*)(smem + OFF_CODES);
    float* zs    = (float*)(smem + OFF_ZS);
    float* ep    = (float*)(smem + OFF_EP);

    const int tid  = threadIdx.x;
    const int b    = blockIdx.x;
    const int lane = tid & 31;
    const int warp = tid >> 5;

    // ---- cp.async W into smem ----
    {
        uint32_t ws = (uint32_t)__cvta_generic_to_shared(smem + OFF_W);
        const char* wg = (const char*)g_Wbf;
        for (int i = tid; i < SZ_W / 16; i += THREADS)
            asm volatile("cp.async.cg.shared.global [%0], [%1], 16;"
                         :: "r"(ws + i * 16), "l"(wg + i * 16));
        asm volatile("cp.async.commit_group;");
    }

    // ---- stage indices (padded to 256) ----
    for (int i = tid; i < 2 * NCTX; i += THREADS) {
        int v = xs_xt[b * 2 * NCTX + i];
        if (i & 1) txi[i >> 1] = v; else sxi[i >> 1] = v;
    }
    if (tid < NCTX) pxi[tid] = path_idx[b * NCTX + tid];
    if (tid < 56) { sxi[NCTX + tid] = 0; pxi[NCTX + tid] = 0; txi[NCTX + tid] = 0; }
    if (tid < D) avs[tid] = att_vec[tid];
    __syncthreads();

    // ---- gather tile 0 ----
    gather_tile(smem, sxi, pxi, txi, value_vocab, path_vocab, 0, tid);
    asm volatile("cp.async.wait_group 0;");
    __syncthreads();

    // ---- warp tiling: 4 m-warps (32 rows) x 4 n-warps (32 cols), m32n32 per warp ----
    const int mwarp = warp & 3;
    const int nwarp = warp >> 2;
    const int g  = lane >> 2;
    const int tg = lane & 3;

    const uint32_t ctx_s = (uint32_t)__cvta_generic_to_shared(smem + OFF_CTX);
    const uint32_t w_s   = (uint32_t)__cvta_generic_to_shared(smem + OFF_W);

    // A ldmatrix lane addresses (two m16 frags)
    const uint32_t a_off0 = (uint32_t)((mwarp * 32 + (lane & 15)) * CTX_BSTRIDE + (lane >> 4) * 16);
    const uint32_t a_off1 = a_off0 + 16 * CTX_BSTRIDE;
    // B ldmatrix lane addresses (two n16 frags)
    const int bc = ((lane >> 4) << 3) + (lane & 7);
    const uint32_t b_off0 = (uint32_t)((nwarp * 32 + bc) * CTX_BSTRIDE + ((lane >> 3) & 1) * 16);
    const uint32_t b_off1 = b_off0 + 16 * CTX_BSTRIDE;

    // av registers for this thread's 8 columns: col(jj,c2) = nwarp*32 + (jj>>1)*16 + (jj&1)*8 + tg*2 + c2
    float av8[8];
#pragma unroll
    for (int jj = 0; jj < 4; jj++) {
        int col = nwarp * 32 + (jj >> 1) * 16 + (jj & 1) * 8 + tg * 2;
        av8[jj * 2]     = avs[col];
        av8[jj * 2 + 1] = avs[col + 1];
    }

    float cpart[8];
#pragma unroll
    for (int i = 0; i < 8; i++) cpart[i] = 0.f;
    float resum = 0.f;

    for (int t = 0; t < NTILES; t++) {
        // ---- GEMM: acc[m][jj][c] over k=384 ----
        float acc[2][4][4];
#pragma unroll
        for (int m = 0; m < 2; m++)
#pragma unroll
            for (int jj = 0; jj < 4; jj++)
#pragma unroll
                for (int c = 0; c < 4; c++) acc[m][jj][c] = 0.f;

#pragma unroll
        for (int kk = 0; kk < F / 16; kk++) {
            uint32_t a[2][4], bq[2][4];
            ldsm_x4(a[0][0], a[0][1], a[0][2], a[0][3], ctx_s + a_off0 + kk * 32);
            ldsm_x4(a[1][0], a[1][1], a[1][2], a[1][3], ctx_s + a_off1 + kk * 32);
            ldsm_x4(bq[0][0], bq[0][1], bq[0][2], bq[0][3], w_s + b_off0 + kk * 32);
            ldsm_x4(bq[1][0], bq[1][1], bq[1][2], bq[1][3], w_s + b_off1 + kk * 32);
#pragma unroll
            for (int m = 0; m < 2; m++) {
#pragma unroll
                for (int n16 = 0; n16 < 2; n16++) {
                    mma16816(acc[m][n16 * 2],     a[m][0], a[m][1], a[m][2], a[m][3],
                             bq[n16][0], bq[n16][1]);
                    mma16816(acc[m][n16 * 2 + 1], a[m][0], a[m][1], a[m][2], a[m][3],
                             bq[n16][2], bq[n16][3]);
                }
            }
        }

        // ---- tanh in place + score partials ----
#pragma unroll
        for (int m = 0; m < 2; m++)
#pragma unroll
            for (int jj = 0; jj < 4; jj++)
#pragma unroll
                for (int c = 0; c < 4; c++)
                    acc[m][jj][c] = fast_tanhf(acc[m][jj][c]);

        // p[m][h]: row = mwarp*32 + m*16 + h*8 + g
#pragma unroll
        for (int m = 0; m < 2; m++) {
#pragma unroll
            for (int h = 0; h < 2; h++) {
                float p = 0.f;
#pragma unroll
                for (int jj = 0; jj < 4; jj++) {
                    p += av8[jj * 2]     * acc[m][jj][h * 2];
                    p += av8[jj * 2 + 1] * acc[m][jj][h * 2 + 1];
                }
                p += __shfl_xor_sync(0xFFFFFFFFu, p, 1);
                p += __shfl_xor_sync(0xFFFFFFFFu, p, 2);
                if (tg == 0) {
                    int row = mwarp * 32 + m * 16 + h * 8 + g;
                    sp[row * 4 + nwarp] = p;
                }
            }
        }
        __syncthreads();

        if (tid < TILE_N) {
            float s = sp[tid * 4] + sp[tid * 4 + 1] + sp[tid * 4 + 2] + sp[tid * 4 + 3];
            float e = (t * TILE_N + tid < NCTX) ? __expf(s) : 0.f;
            esc[tid] = e;
            resum += e;
        }
        __syncthreads();

        // ---- weighted accumulation from registers ----
#pragma unroll
        for (int m = 0; m < 2; m++) {
#pragma unroll
            for (int h = 0; h < 2; h++) {
                float e = esc[mwarp * 32 + m * 16 + h * 8 + g];
#pragma unroll
                for (int jj = 0; jj < 4; jj++) {
                    cpart[jj * 2]     += e * acc[m][jj][h * 2];
                    cpart[jj * 2 + 1] += e * acc[m][jj][h * 2 + 1];
                }
            }
        }

        // ---- gather next tile (ctx free: all warps past GEMM via syncs above) ----
        if (t + 1 < NTILES) {
            gather_tile(smem, sxi, pxi, txi, value_vocab, path_vocab, (t + 1) * TILE_N, tid);
            __syncthreads();
        }
    }

    // ---- reduce cpart across g (lanes 4,8,16), write per-mwarp col partials ----
#pragma unroll
    for (int off = 4; off < 32; off <<= 1)
#pragma unroll
        for (int i = 0; i < 8; i++)
            cpart[i] += __shfl_xor_sync(0xFFFFFFFFu, cpart[i], off);
    if (g == 0) {
#pragma unroll
        for (int jj = 0; jj < 4; jj++) {
            int col = nwarp * 32 + (jj >> 1) * 16 + (jj & 1) * 8 + tg * 2;
            codep[col * 4 + mwarp]       = cpart[jj * 2];
            codep[(col + 1) * 4 + mwarp] = cpart[jj * 2 + 1];
        }
    }
    // esum partial reduce (threads 0-127 hold resum)
    if (tid < TILE_N) {
        float s = resum;
#pragma unroll
        for (int off = 16; off > 0; off >>= 1)
            s += __shfl_xor_sync(0xFFFFFFFFu, s, off);
        if (lane == 0) ep[warp] = s;
    }
    __syncthreads();

    float esum = ep[0] + ep[1] + ep[2] + ep[3];
    if (tid < D) {
        float c = codep[tid * 4] + codep[tid * 4 + 1] + codep[tid * 4 + 2] + codep[tid * 4 + 3];
        codes[tid] = c / esum;
    }
    __syncthreads();

    // ---- dense + sigmoid (512 threads, 4 d-chunks) ----
    {
        const int grp = tid >> 7, dcol = tid & 127;
        float z = 0.f;
#pragma unroll 8
        for (int d2 = 0; d2 < 32; d2++) {
            int d = grp * 32 + d2;
            z += codes[d] * dense_w[d * OUTD + dcol];
        }
        if (grp != 0) zs[(grp - 1) * 128 + dcol] = z;
        __syncthreads();
        if (grp == 0) {
            float zz = z + zs[dcol] + zs[128 + dcol] + zs[256 + dcol] + dense_b[dcol];
            out[b * OUTD + dcol] = 1.f / (1.f + __expf(-zz));
        }
    }
}

extern "C" void kernel_launch(void* const* d_in, const int* in_sizes, int n_in,
                              void* d_out, int out_size)
{
    const int*   xs_xt       = (const int*)d_in[0];
    const int*   path_idx    = (const int*)d_in[1];
    const float* value_vocab = (const float*)d_in[2];
    const float* path_vocab  = (const float*)d_in[3];
    const float* W           = (const float*)d_in[4];
    const float* att_vec     = (const float*)d_in[5];
    const float* dense_w     = (const float*)d_in[6];
    const float* dense_b     = (const float*)d_in[7];
    float*       out         = (float*)d_out;

    prep_w_kernel<<<48, 256>>>(W);

    cudaFuncSetAttribute(acv_fused_kernel,
                         cudaFuncAttributeMaxDynamicSharedMemorySize, SMEM_BYTES);
    acv_fused_kernel<<<1024, THREADS, SMEM_BYTES>>>(
        xs_xt, path_idx, value_vocab, path_vocab, att_vec,
        dense_w, dense_b, out);
}

// round 6
// speedup vs baseline: 2.8732x; 1.0123x over previous
#include <cuda_runtime.h>
#include <cuda_bf16.h>
#include <stdint.h>

// Problem constants
#define NCTX      200
#define D         128
#define F         384
#define OUTD      128
#define THREADS   512
#define TILE_N    128
#define NTILES    2            // 2 x 128 = 256 rows (padded; invalid rows idx=0, esc=0)

#define CTX_BSTRIDE  400       // bytes per ctx/W row (384 fp8 + 16 pad)

// ---- smem layout (bytes) ----
#define OFF_W      0
#define SZ_W       (D * CTX_BSTRIDE)              // 51200
#define OFF_CTX0   (OFF_W + SZ_W)                 // 51200
#define SZ_CTX     (TILE_N * CTX_BSTRIDE)         // 51200
#define OFF_CTX1   (OFF_CTX0 + SZ_CTX)            // 102400
#define OFF_IDX    (OFF_CTX1 + SZ_CTX)            // 153600 : 3*256*4 = 3072
#define OFF_AV     (OFF_IDX + 3072)               // 512
#define OFF_SP     (OFF_AV + 512)                 // 2048
#define OFF_ESC    (OFF_SP + 2048)                // 512
#define OFF_CODEP  (OFF_ESC + 512)                // 2048
#define OFF_CODES  (OFF_CODEP + 2048)             // 512
#define OFF_ZS     (OFF_CODES + 512)              // 1536
#define OFF_EP     (OFF_ZS + 1536)                // 64
#define SMEM_BYTES (OFF_EP + 64)                  // 163904

// W pre-converted to e4m3, row stride 400 B
__device__ __align__(16) unsigned char g_Wf8[SZ_W];

__device__ __forceinline__ uint32_t pack4_e4m3(float4 v) {
    uint16_t lo, hi;
    asm("cvt.rn.satfinite.e4m3x2.f32 %0, %1, %2;" : "=h"(lo) : "f"(v.y), "f"(v.x));
    asm("cvt.rn.satfinite.e4m3x2.f32 %0, %1, %2;" : "=h"(hi) : "f"(v.w), "f"(v.z));
    return (uint32_t)lo | ((uint32_t)hi << 16);
}

__global__ void prep_w_kernel(const float* __restrict__ W) {
    int i = blockIdx.x * 256 + threadIdx.x;      // 0..12287 (128 rows x 96 quads)
    int d = i / 96, j = i % 96;
    float4 v = ((const float4*)W)[i];
    *(uint32_t*)(g_Wf8 + d * CTX_BSTRIDE + j * 4) = pack4_e4m3(v);
}

__device__ __forceinline__ float fast_tanhf(float x) {
    float y; asm("tanh.approx.f32 %0, %1;" : "=f"(y) : "f"(x)); return y;
}
__device__ __forceinline__ void mma_f8(float* acc, uint32_t a0, uint32_t a1,
                                       uint32_t a2, uint32_t a3,
                                       uint32_t b0, uint32_t b1) {
    asm volatile(
        "mma.sync.aligned.m16n8k32.row.col.f32.e4m3.e4m3.f32 "
        "{%0,%1,%2,%3},{%4,%5,%6,%7},{%8,%9},{%0,%1,%2,%3};"
        : "+f"(acc[0]), "+f"(acc[1]), "+f"(acc[2]), "+f"(acc[3])
        : "r"(a0), "r"(a1), "r"(a2), "r"(a3), "r"(b0), "r"(b1));
}
__device__ __forceinline__ void ldsm_x4(uint32_t& r0, uint32_t& r1,
                                        uint32_t& r2, uint32_t& r3, uint32_t saddr) {
    asm volatile("ldmatrix.sync.aligned.m8n8.x4.shared.b16 {%0,%1,%2,%3}, [%4];"
                 : "=r"(r0), "=r"(r1), "=r"(r2), "=r"(r3) : "r"(saddr));
}
__device__ __forceinline__ float4 ldg_nc_v4(const float* p) {
    float4 r;
    asm volatile("ld.global.nc.v4.f32 {%0,%1,%2,%3}, [%4];"
                 : "=f"(r.x), "=f"(r.y), "=f"(r.z), "=f"(r.w) : "l"(p));
    return r;
}

// load one prefetch chunk (2 quads) for tile starting at n0
__device__ __forceinline__ void load_chunk(int c, int n0, int tid,
                                           const int* sxi, const int* pxi, const int* txi,
                                           const float* value_vocab, const float* path_vocab,
                                           float4* v, int* soff) {
#pragma unroll
    for (int u = 0; u < 2; u++) {
        int i = tid + (c * 2 + u) * THREADS;
        int r = i / 96, q = i - r * 96;
        int seg = q >> 5, j = q & 31;
        int idx = (seg == 0) ? sxi[n0 + r] : (seg == 1) ? pxi[n0 + r] : txi[n0 + r];
        const float* tab = (seg == 1) ? path_vocab : value_vocab;
        v[u] = ldg_nc_v4(tab + (size_t)idx * 128 + j * 4);
        soff[u] = r * CTX_BSTRIDE + q * 4;
    }
}
__device__ __forceinline__ void store_chunk(unsigned char* buf, const float4* v, const int* soff) {
#pragma unroll
    for (int u = 0; u < 2; u++)
        *(uint32_t*)(buf + soff[u]) = pack4_e4m3(v[u]);
}

__global__ void __launch_bounds__(THREADS, 1)
acv_fused_kernel(const int* __restrict__ xs_xt,
                 const int* __restrict__ path_idx,
                 const float* __restrict__ value_vocab,
                 const float* __restrict__ path_vocab,
                 const float* __restrict__ att_vec,
                 const float* __restrict__ dense_w,
                 const float* __restrict__ dense_b,
                 float* __restrict__ out)
{
    extern __shared__ unsigned char smem[];
    int*   sxi   = (int*)(smem + OFF_IDX);
    int*   pxi   = sxi + 256;
    int*   txi   = pxi + 256;
    float* avs   = (float*)(smem + OFF_AV);
    float* sp    = (float*)(smem + OFF_SP);
    float* esc   = (float*)(smem + OFF_ESC);
    float* codep = (float*)(smem + OFF_CODEP);
    float* codes = (float*)(smem + OFF_CODES);
    float* zs    = (float*)(smem + OFF_ZS);
    float* ep    = (float*)(smem + OFF_EP);

    const int tid  = threadIdx.x;
    const int b    = blockIdx.x;
    const int lane = tid & 31;
    const int warp = tid >> 5;

    // ---- cp.async W (pre-converted fp8) into smem ----
    {
        uint32_t ws = (uint32_t)__cvta_generic_to_shared(smem + OFF_W);
        const char* wg = (const char*)g_Wf8;
        for (int i = tid; i < SZ_W / 16; i += THREADS)
            asm volatile("cp.async.cg.shared.global [%0], [%1], 16;"
                         :: "r"(ws + i * 16), "l"(wg + i * 16));
        asm volatile("cp.async.commit_group;");
    }

    // ---- stage indices (padded to 256) ----
    for (int i = tid; i < 2 * NCTX; i += THREADS) {
        int v = xs_xt[b * 2 * NCTX + i];
        if (i & 1) txi[i >> 1] = v; else sxi[i >> 1] = v;
    }
    if (tid < NCTX) pxi[tid] = path_idx[b * NCTX + tid];
    if (tid < 56) { sxi[NCTX + tid] = 0; pxi[NCTX + tid] = 0; txi[NCTX + tid] = 0; }
    if (tid < D) avs[tid] = att_vec[tid];
    __syncthreads();

    // ---- gather tile 0 (24 quads/thread, chunks of 4) ----
    {
        unsigned char* buf = smem + OFF_CTX0;
        for (int s = 0; s < 24; s += 4) {
            float4 v[4]; int soff[4];
#pragma unroll
            for (int u = 0; u < 4; u++) {
                int i = tid + (s + u) * THREADS;
                int r = i / 96, q = i - r * 96;
                int seg = q >> 5, j = q & 31;
                int idx = (seg == 0) ? sxi[r] : (seg == 1) ? pxi[r] : txi[r];
                const float* tab = (seg == 1) ? path_vocab : value_vocab;
                v[u] = ldg_nc_v4(tab + (size_t)idx * 128 + j * 4);
                soff[u] = r * CTX_BSTRIDE + q * 4;
            }
#pragma unroll
            for (int u = 0; u < 4; u++)
                *(uint32_t*)(buf + soff[u]) = pack4_e4m3(v[u]);
        }
    }
    asm volatile("cp.async.wait_group 0;");
    __syncthreads();

    // ---- warp tiling: 4 m-warps x 4 n-warps, m32n32 per warp ----
    const int mwarp = warp & 3;
    const int nwarp = warp >> 2;
    const int g  = lane >> 2;
    const int tg = lane & 3;

    const uint32_t ctx0_s = (uint32_t)__cvta_generic_to_shared(smem + OFF_CTX0);
    const uint32_t w_s    = (uint32_t)__cvta_generic_to_shared(smem + OFF_W);

    const uint32_t a_off0 = (uint32_t)((mwarp * 32 + (lane & 15)) * CTX_BSTRIDE + (lane >> 4) * 16);
    const uint32_t a_off1 = a_off0 + 16 * CTX_BSTRIDE;
    const int bc = ((lane >> 4) << 3) + (lane & 7);
    const uint32_t b_off0 = (uint32_t)((nwarp * 32 + bc) * CTX_BSTRIDE + ((lane >> 3) & 1) * 16);
    const uint32_t b_off1 = b_off0 + 16 * CTX_BSTRIDE;

    float av8[8];
#pragma unroll
    for (int jj = 0; jj < 4; jj++) {
        int col = nwarp * 32 + (jj >> 1) * 16 + (jj & 1) * 8 + tg * 2;
        av8[jj * 2]     = avs[col];
        av8[jj * 2 + 1] = avs[col + 1];
    }

    float cpart[8];
#pragma unroll
    for (int i = 0; i < 8; i++) cpart[i] = 0.f;
    float resum = 0.f;

    for (int t = 0; t < NTILES; t++) {
        const bool hn = (t + 1 < NTILES);
        const int  n1 = (t + 1) * TILE_N;
        unsigned char* nbuf = smem + OFF_CTX0 + ((t + 1) & 1) * SZ_CTX;
        const uint32_t ctx_s = ctx0_s + (t & 1) * SZ_CTX;

        // prefetch pipeline prologue (chunks 0,1 of next tile)
        float4 pv[2][2]; int po[2][2];
        if (hn) {
            load_chunk(0, n1, tid, sxi, pxi, txi, value_vocab, path_vocab, pv[0], po[0]);
            load_chunk(1, n1, tid, sxi, pxi, txi, value_vocab, path_vocab, pv[1], po[1]);
        }

        // ---- GEMM: 12 k32-steps ----
        float acc[2][4][4];
#pragma unroll
        for (int m = 0; m < 2; m++)
#pragma unroll
            for (int jj = 0; jj < 4; jj++)
#pragma unroll
                for (int c = 0; c < 4; c++) acc[m][jj][c] = 0.f;

#pragma unroll
        for (int kk = 0; kk < 12; kk++) {
            uint32_t a[2][4], bq[2][4];
            ldsm_x4(a[0][0], a[0][1], a[0][2], a[0][3], ctx_s + a_off0 + kk * 32);
            ldsm_x4(a[1][0], a[1][1], a[1][2], a[1][3], ctx_s + a_off1 + kk * 32);
            ldsm_x4(bq[0][0], bq[0][1], bq[0][2], bq[0][3], w_s + b_off0 + kk * 32);
            ldsm_x4(bq[1][0], bq[1][1], bq[1][2], bq[1][3], w_s + b_off1 + kk * 32);
#pragma unroll
            for (int m = 0; m < 2; m++) {
#pragma unroll
                for (int n16 = 0; n16 < 2; n16++) {
                    mma_f8(acc[m][n16 * 2],     a[m][0], a[m][1], a[m][2], a[m][3],
                           bq[n16][0], bq[n16][1]);
                    mma_f8(acc[m][n16 * 2 + 1], a[m][0], a[m][1], a[m][2], a[m][3],
                           bq[n16][2], bq[n16][3]);
                }
            }
            if (hn) {
                // depth-2 rotate: store chunk kk, refill with chunk kk+2
                store_chunk(nbuf, pv[kk & 1], po[kk & 1]);
                if (kk < 10)
                    load_chunk(kk + 2, n1, tid, sxi, pxi, txi,
                               value_vocab, path_vocab, pv[kk & 1], po[kk & 1]);
            }
        }

        // ---- tanh in place + score partials ----
#pragma unroll
        for (int m = 0; m < 2; m++)
#pragma unroll
            for (int jj = 0; jj < 4; jj++)
#pragma unroll
                for (int c = 0; c < 4; c++)
                    acc[m][jj][c] = fast_tanhf(acc[m][jj][c]);

#pragma unroll
        for (int m = 0; m < 2; m++) {
#pragma unroll
            for (int h = 0; h < 2; h++) {
                float p = 0.f;
#pragma unroll
                for (int jj = 0; jj < 4; jj++) {
                    p += av8[jj * 2]     * acc[m][jj][h * 2];
                    p += av8[jj * 2 + 1] * acc[m][jj][h * 2 + 1];
                }
                p += __shfl_xor_sync(0xFFFFFFFFu, p, 1);
                p += __shfl_xor_sync(0xFFFFFFFFu, p, 2);
                if (tg == 0) {
                    int row = mwarp * 32 + m * 16 + h * 8 + g;
                    sp[row * 4 + nwarp] = p;
                }
            }
        }
        __syncthreads();

        if (tid < TILE_N) {
            float s = sp[tid * 4] + sp[tid * 4 + 1] + sp[tid * 4 + 2] + sp[tid * 4 + 3];
            float e = (t * TILE_N + tid < NCTX) ? __expf(s) : 0.f;
            esc[tid] = e;
            resum += e;
        }
        __syncthreads();

        // ---- weighted accumulation from registers ----
#pragma unroll
        for (int m = 0; m < 2; m++) {
#pragma unroll
            for (int h = 0; h < 2; h++) {
                float e = esc[mwarp * 32 + m * 16 + h * 8 + g];
#pragma unroll
                for (int jj = 0; jj < 4; jj++) {
                    cpart[jj * 2]     += e * acc[m][jj][h * 2];
                    cpart[jj * 2 + 1] += e * acc[m][jj][h * 2 + 1];
                }
            }
        }
    }

    // ---- reduce cpart across g, write per-mwarp col partials ----
#pragma unroll
    for (int off = 4; off < 32; off <<= 1)
#pragma unroll
        for (int i = 0; i < 8; i++)
            cpart[i] += __shfl_xor_sync(0xFFFFFFFFu, cpart[i], off);
    if (g == 0) {
#pragma unroll
        for (int jj = 0; jj < 4; jj++) {
            int col = nwarp * 32 + (jj >> 1) * 16 + (jj & 1) * 8 + tg * 2;
            codep[col * 4 + mwarp]       = cpart[jj * 2];
            codep[(col + 1) * 4 + mwarp] = cpart[jj * 2 + 1];
        }
    }
    if (tid < TILE_N) {
        float s = resum;
#pragma unroll
        for (int off = 16; off > 0; off >>= 1)
            s += __shfl_xor_sync(0xFFFFFFFFu, s, off);
        if (lane == 0) ep[warp] = s;
    }
    __syncthreads();

    float esum = ep[0] + ep[1] + ep[2] + ep[3];
    if (tid < D) {
        float c = codep[tid * 4] + codep[tid * 4 + 1] + codep[tid * 4 + 2] + codep[tid * 4 + 3];
        codes[tid] = c / esum;
    }
    __syncthreads();

    // ---- dense + sigmoid ----
    {
        const int grp = tid >> 7, dcol = tid & 127;
        float z = 0.f;
#pragma unroll 8
        for (int d2 = 0; d2 < 32; d2++) {
            int d = grp * 32 + d2;
            z += codes[d] * dense_w[d * OUTD + dcol];
        }
        if (grp != 0) zs[(grp - 1) * 128 + dcol] = z;
        __syncthreads();
        if (grp == 0) {
            float zz = z + zs[dcol] + zs[128 + dcol] + zs[256 + dcol] + dense_b[dcol];
            out[b * OUTD + dcol] = 1.f / (1.f + __expf(-zz));
        }
    }
}

extern "C" void kernel_launch(void* const* d_in, const int* in_sizes, int n_in,
                              void* d_out, int out_size)
{
    const int*   xs_xt       = (const int*)d_in[0];
    const int*   path_idx    = (const int*)d_in[1];
    const float* value_vocab = (const float*)d_in[2];
    const float* path_vocab  = (const float*)d_in[3];
    const float* W           = (const float*)d_in[4];
    const float* att_vec     = (const float*)d_in[5];
    const float* dense_w     = (const float*)d_in[6];
    const float* dense_b     = (const float*)d_in[7];
    float*       out         = (float*)d_out;

    prep_w_kernel<<<48, 256>>>(W);

    cudaFuncSetAttribute(acv_fused_kernel,
                         cudaFuncAttributeMaxDynamicSharedMemorySize, SMEM_BYTES);
    acv_fused_kernel<<<1024, THREADS, SMEM_BYTES>>>(
        xs_xt, path_idx, value_vocab, path_vocab, att_vec,
        dense_w, dense_b, out);
}

// round 7
// speedup vs baseline: 2.8845x; 1.0039x over previous
#include <cuda_runtime.h>
#include <cuda_bf16.h>
#include <stdint.h>

// Problem constants
#define NCTX      200
#define D         128
#define F         384
#define OUTD      128
#define THREADS   512
#define TILE_N    128
#define NTILES    2            // 2 x 128 = 256 rows (padded; invalid rows idx=0, esc=0)

#define CTX_BSTRIDE  400       // bytes per ctx/W row (384 fp8 + 16 pad)

// ---- smem layout (bytes) ----
#define OFF_W      0
#define SZ_W       (D * CTX_BSTRIDE)              // 51200
#define OFF_CTX0   (OFF_W + SZ_W)                 // 51200
#define SZ_CTX     (TILE_N * CTX_BSTRIDE)         // 51200
#define OFF_CTX1   (OFF_CTX0 + SZ_CTX)            // 102400
#define OFF_IDX    (OFF_CTX1 + SZ_CTX)            // 153600 : 3*256*4 = 3072
#define OFF_AV     (OFF_IDX + 3072)               // 512
#define OFF_SP     (OFF_AV + 512)                 // 2048
#define OFF_ESC    (OFF_SP + 2048)                // 512
#define OFF_CODEP  (OFF_ESC + 512)                // 2048
#define OFF_CODES  (OFF_CODEP + 2048)             // 512
#define OFF_ZS     (OFF_CODES + 512)              // 1536
#define OFF_EP     (OFF_ZS + 1536)                // 64
#define SMEM_BYTES (OFF_EP + 64)                  // 163904

// W pre-converted to e4m3, row stride 400 B
__device__ __align__(16) unsigned char g_Wf8[SZ_W];

__device__ __forceinline__ uint32_t pack4_e4m3(float4 v) {
    uint16_t lo, hi;
    asm("cvt.rn.satfinite.e4m3x2.f32 %0, %1, %2;" : "=h"(lo) : "f"(v.y), "f"(v.x));
    asm("cvt.rn.satfinite.e4m3x2.f32 %0, %1, %2;" : "=h"(hi) : "f"(v.w), "f"(v.z));
    return (uint32_t)lo | ((uint32_t)hi << 16);
}

__global__ void prep_w_kernel(const float* __restrict__ W) {
    int i = blockIdx.x * 256 + threadIdx.x;      // 0..12287 (128 rows x 96 quads)
    int d = i / 96, j = i % 96;
    float4 v = ((const float4*)W)[i];
    *(uint32_t*)(g_Wf8 + d * CTX_BSTRIDE + j * 4) = pack4_e4m3(v);
}

__device__ __forceinline__ float fast_tanhf(float x) {
    float y; asm("tanh.approx.f32 %0, %1;" : "=f"(y) : "f"(x)); return y;
}
__device__ __forceinline__ void mma_f8(float* acc, uint32_t a0, uint32_t a1,
                                       uint32_t a2, uint32_t a3,
                                       uint32_t b0, uint32_t b1) {
    asm volatile(
        "mma.sync.aligned.m16n8k32.row.col.f32.e4m3.e4m3.f32 "
        "{%0,%1,%2,%3},{%4,%5,%6,%7},{%8,%9},{%0,%1,%2,%3};"
        : "+f"(acc[0]), "+f"(acc[1]), "+f"(acc[2]), "+f"(acc[3])
        : "r"(a0), "r"(a1), "r"(a2), "r"(a3), "r"(b0), "r"(b1));
}
__device__ __forceinline__ void ldsm_x4(uint32_t& r0, uint32_t& r1,
                                        uint32_t& r2, uint32_t& r3, uint32_t saddr) {
    asm volatile("ldmatrix.sync.aligned.m8n8.x4.shared.b16 {%0,%1,%2,%3}, [%4];"
                 : "=r"(r0), "=r"(r1), "=r"(r2), "=r"(r3) : "r"(saddr));
}
__device__ __forceinline__ float4 ldg_nc_v4(const float* p) {
    float4 r;
    asm volatile("ld.global.nc.v4.f32 {%0,%1,%2,%3}, [%4];"
                 : "=f"(r.x), "=f"(r.y), "=f"(r.z), "=f"(r.w) : "l"(p));
    return r;
}

// load one prefetch chunk (2 quads) for tile starting at n0
__device__ __forceinline__ void load_chunk(int c, int n0, int tid,
                                           const int* sxi, const int* pxi, const int* txi,
                                           const float* value_vocab, const float* path_vocab,
                                           float4* v, int* soff) {
#pragma unroll
    for (int u = 0; u < 2; u++) {
        int i = tid + (c * 2 + u) * THREADS;
        int r = i / 96, q = i - r * 96;
        int seg = q >> 5, j = q & 31;
        int idx = (seg == 0) ? sxi[n0 + r] : (seg == 1) ? pxi[n0 + r] : txi[n0 + r];
        const float* tab = (seg == 1) ? path_vocab : value_vocab;
        v[u] = ldg_nc_v4(tab + (size_t)idx * 128 + j * 4);
        soff[u] = r * CTX_BSTRIDE + q * 4;
    }
}
__device__ __forceinline__ void store_chunk(unsigned char* buf, const float4* v, const int* soff) {
#pragma unroll
    for (int u = 0; u < 2; u++)
        *(uint32_t*)(buf + soff[u]) = pack4_e4m3(v[u]);
}

__global__ void __launch_bounds__(THREADS, 1)
acv_fused_kernel(const int* __restrict__ xs_xt,
                 const int* __restrict__ path_idx,
                 const float* __restrict__ value_vocab,
                 const float* __restrict__ path_vocab,
                 const float* __restrict__ att_vec,
                 const float* __restrict__ dense_w,
                 const float* __restrict__ dense_b,
                 float* __restrict__ out)
{
    extern __shared__ unsigned char smem[];
    int*   sxi   = (int*)(smem + OFF_IDX);
    int*   pxi   = sxi + 256;
    int*   txi   = pxi + 256;
    float* avs   = (float*)(smem + OFF_AV);
    float* sp    = (float*)(smem + OFF_SP);
    float* esc   = (float*)(smem + OFF_ESC);
    float* codep = (float*)(smem + OFF_CODEP);
    float* codes = (float*)(smem + OFF_CODES);
    float* zs    = (float*)(smem + OFF_ZS);
    float* ep    = (float*)(smem + OFF_EP);

    const int tid  = threadIdx.x;
    const int b    = blockIdx.x;
    const int lane = tid & 31;
    const int warp = tid >> 5;

    // ---- cp.async W (pre-converted fp8) into smem ----
    {
        uint32_t ws = (uint32_t)__cvta_generic_to_shared(smem + OFF_W);
        const char* wg = (const char*)g_Wf8;
        for (int i = tid; i < SZ_W / 16; i += THREADS)
            asm volatile("cp.async.cg.shared.global [%0], [%1], 16;"
                         :: "r"(ws + i * 16), "l"(wg + i * 16));
        asm volatile("cp.async.commit_group;");
    }

    // ---- stage indices (padded to 256) ----
    for (int i = tid; i < 2 * NCTX; i += THREADS) {
        int v = xs_xt[b * 2 * NCTX + i];
        if (i & 1) txi[i >> 1] = v; else sxi[i >> 1] = v;
    }
    if (tid < NCTX) pxi[tid] = path_idx[b * NCTX + tid];
    if (tid < 56) { sxi[NCTX + tid] = 0; pxi[NCTX + tid] = 0; txi[NCTX + tid] = 0; }
    if (tid < D) avs[tid] = att_vec[tid];
    __syncthreads();

    // ---- gather tile 0 (24 quads/thread, chunks of 4) ----
    {
        unsigned char* buf = smem + OFF_CTX0;
        for (int s = 0; s < 24; s += 4) {
            float4 v[4]; int soff[4];
#pragma unroll
            for (int u = 0; u < 4; u++) {
                int i = tid + (s + u) * THREADS;
                int r = i / 96, q = i - r * 96;
                int seg = q >> 5, j = q & 31;
                int idx = (seg == 0) ? sxi[r] : (seg == 1) ? pxi[r] : txi[r];
                const float* tab = (seg == 1) ? path_vocab : value_vocab;
                v[u] = ldg_nc_v4(tab + (size_t)idx * 128 + j * 4);
                soff[u] = r * CTX_BSTRIDE + q * 4;
            }
#pragma unroll
            for (int u = 0; u < 4; u++)
                *(uint32_t*)(buf + soff[u]) = pack4_e4m3(v[u]);
        }
    }
    asm volatile("cp.async.wait_group 0;");
    __syncthreads();

    // ---- warp tiling: 4 m-warps x 4 n-warps, m32n32 per warp ----
    const int mwarp = warp & 3;
    const int nwarp = warp >> 2;
    const int g  = lane >> 2;
    const int tg = lane & 3;

    const uint32_t ctx0_s = (uint32_t)__cvta_generic_to_shared(smem + OFF_CTX0);
    const uint32_t w_s    = (uint32_t)__cvta_generic_to_shared(smem + OFF_W);

    const uint32_t a_off0 = (uint32_t)((mwarp * 32 + (lane & 15)) * CTX_BSTRIDE + (lane >> 4) * 16);
    const uint32_t a_off1 = a_off0 + 16 * CTX_BSTRIDE;
    const int bc = ((lane >> 4) << 3) + (lane & 7);
    const uint32_t b_off0 = (uint32_t)((nwarp * 32 + bc) * CTX_BSTRIDE + ((lane >> 3) & 1) * 16);
    const uint32_t b_off1 = b_off0 + 16 * CTX_BSTRIDE;

    float av8[8];
#pragma unroll
    for (int jj = 0; jj < 4; jj++) {
        int col = nwarp * 32 + (jj >> 1) * 16 + (jj & 1) * 8 + tg * 2;
        av8[jj * 2]     = avs[col];
        av8[jj * 2 + 1] = avs[col + 1];
    }

    float cpart[8];
#pragma unroll
    for (int i = 0; i < 8; i++) cpart[i] = 0.f;
    float resum = 0.f;

    for (int t = 0; t < NTILES; t++) {
        const bool hn = (t + 1 < NTILES);
        const int  n1 = (t + 1) * TILE_N;
        unsigned char* nbuf = smem + OFF_CTX0 + ((t + 1) & 1) * SZ_CTX;
        const uint32_t ctx_s = ctx0_s + (t & 1) * SZ_CTX;

        // prefetch pipeline prologue (chunks 0,1 of next tile)
        float4 pv[2][2]; int po[2][2];
        if (hn) {
            load_chunk(0, n1, tid, sxi, pxi, txi, value_vocab, path_vocab, pv[0], po[0]);
            load_chunk(1, n1, tid, sxi, pxi, txi, value_vocab, path_vocab, pv[1], po[1]);
        }

        // ---- GEMM: 12 k32-steps ----
        float acc[2][4][4];
#pragma unroll
        for (int m = 0; m < 2; m++)
#pragma unroll
            for (int jj = 0; jj < 4; jj++)
#pragma unroll
                for (int c = 0; c < 4; c++) acc[m][jj][c] = 0.f;

#pragma unroll
        for (int kk = 0; kk < 12; kk++) {
            uint32_t a[2][4], bq[2][4];
            ldsm_x4(a[0][0], a[0][1], a[0][2], a[0][3], ctx_s + a_off0 + kk * 32);
            ldsm_x4(a[1][0], a[1][1], a[1][2], a[1][3], ctx_s + a_off1 + kk * 32);
            ldsm_x4(bq[0][0], bq[0][1], bq[0][2], bq[0][3], w_s + b_off0 + kk * 32);
            ldsm_x4(bq[1][0], bq[1][1], bq[1][2], bq[1][3], w_s + b_off1 + kk * 32);
#pragma unroll
            for (int m = 0; m < 2; m++) {
#pragma unroll
                for (int n16 = 0; n16 < 2; n16++) {
                    mma_f8(acc[m][n16 * 2],     a[m][0], a[m][1], a[m][2], a[m][3],
                           bq[n16][0], bq[n16][1]);
                    mma_f8(acc[m][n16 * 2 + 1], a[m][0], a[m][1], a[m][2], a[m][3],
                           bq[n16][2], bq[n16][3]);
                }
            }
            if (hn) {
                // depth-2 rotate: store chunk kk, refill with chunk kk+2
                store_chunk(nbuf, pv[kk & 1], po[kk & 1]);
                if (kk < 10)
                    load_chunk(kk + 2, n1, tid, sxi, pxi, txi,
                               value_vocab, path_vocab, pv[kk & 1], po[kk & 1]);
            }
        }

        // ---- tanh in place + score partials ----
#pragma unroll
        for (int m = 0; m < 2; m++)
#pragma unroll
            for (int jj = 0; jj < 4; jj++)
#pragma unroll
                for (int c = 0; c < 4; c++)
                    acc[m][jj][c] = fast_tanhf(acc[m][jj][c]);

#pragma unroll
        for (int m = 0; m < 2; m++) {
#pragma unroll
            for (int h = 0; h < 2; h++) {
                float p = 0.f;
#pragma unroll
                for (int jj = 0; jj < 4; jj++) {
                    p += av8[jj * 2]     * acc[m][jj][h * 2];
                    p += av8[jj * 2 + 1] * acc[m][jj][h * 2 + 1];
                }
                p += __shfl_xor_sync(0xFFFFFFFFu, p, 1);
                p += __shfl_xor_sync(0xFFFFFFFFu, p, 2);
                if (tg == 0) {
                    int row = mwarp * 32 + m * 16 + h * 8 + g;
                    sp[row * 4 + nwarp] = p;
                }
            }
        }
        __syncthreads();

        if (tid < TILE_N) {
            float s = sp[tid * 4] + sp[tid * 4 + 1] + sp[tid * 4 + 2] + sp[tid * 4 + 3];
            float e = (t * TILE_N + tid < NCTX) ? __expf(s) : 0.f;
            esc[tid] = e;
            resum += e;
        }
        __syncthreads();

        // ---- weighted accumulation from registers ----
#pragma unroll
        for (int m = 0; m < 2; m++) {
#pragma unroll
            for (int h = 0; h < 2; h++) {
                float e = esc[mwarp * 32 + m * 16 + h * 8 + g];
#pragma unroll
                for (int jj = 0; jj < 4; jj++) {
                    cpart[jj * 2]     += e * acc[m][jj][h * 2];
                    cpart[jj * 2 + 1] += e * acc[m][jj][h * 2 + 1];
                }
            }
        }
    }

    // ---- reduce cpart across g, write per-mwarp col partials ----
#pragma unroll
    for (int off = 4; off < 32; off <<= 1)
#pragma unroll
        for (int i = 0; i < 8; i++)
            cpart[i] += __shfl_xor_sync(0xFFFFFFFFu, cpart[i], off);
    if (g == 0) {
#pragma unroll
        for (int jj = 0; jj < 4; jj++) {
            int col = nwarp * 32 + (jj >> 1) * 16 + (jj & 1) * 8 + tg * 2;
            codep[col * 4 + mwarp]       = cpart[jj * 2];
            codep[(col + 1) * 4 + mwarp] = cpart[jj * 2 + 1];
        }
    }
    if (tid < TILE_N) {
        float s = resum;
#pragma unroll
        for (int off = 16; off > 0; off >>= 1)
            s += __shfl_xor_sync(0xFFFFFFFFu, s, off);
        if (lane == 0) ep[warp] = s;
    }
    __syncthreads();

    float esum = ep[0] + ep[1] + ep[2] + ep[3];
    if (tid < D) {
        float c = codep[tid * 4] + codep[tid * 4 + 1] + codep[tid * 4 + 2] + codep[tid * 4 + 3];
        codes[tid] = c / esum;
    }
    __syncthreads();

    // ---- dense + sigmoid ----
    {
        const int grp = tid >> 7, dcol = tid & 127;
        float z = 0.f;
#pragma unroll 8
        for (int d2 = 0; d2 < 32; d2++) {
            int d = grp * 32 + d2;
            z += codes[d] * dense_w[d * OUTD + dcol];
        }
        if (grp != 0) zs[(grp - 1) * 128 + dcol] = z;
        __syncthreads();
        if (grp == 0) {
            float zz = z + zs[dcol] + zs[128 + dcol] + zs[256 + dcol] + dense_b[dcol];
            out[b * OUTD + dcol] = 1.f / (1.f + __expf(-zz));
        }
    }
}

extern "C" void kernel_launch(void* const* d_in, const int* in_sizes, int n_in,
                              void* d_out, int out_size)
{
    const int*   xs_xt       = (const int*)d_in[0];
    const int*   path_idx    = (const int*)d_in[1];
    const float* value_vocab = (const float*)d_in[2];
    const float* path_vocab  = (const float*)d_in[3];
    const float* W           = (const float*)d_in[4];
    const float* att_vec     = (const float*)d_in[5];
    const float* dense_w     = (const float*)d_in[6];
    const float* dense_b     = (const float*)d_in[7];
    float*       out         = (float*)d_out;

    prep_w_kernel<<<48, 256>>>(W);

    cudaFuncSetAttribute(acv_fused_kernel,
                         cudaFuncAttributeMaxDynamicSharedMemorySize, SMEM_BYTES);
    acv_fused_kernel<<<1024, THREADS, SMEM_BYTES>>>(
        xs_xt, path_idx, value_vocab, path_vocab, att_vec,
        dense_w, dense_b, out);
}

// round 8
// speedup vs baseline: 3.2719x; 1.1343x over previous
#include <cuda_runtime.h>
#include <cuda_bf16.h>
#include <stdint.h>

// Problem constants
#define NCTX      200
#define D         128
#define F         384
#define OUTD      128
#define THREADS   512
#define TILE_N    64
#define NTILES    4            // 4 x 64 = 256 rows (padded; invalid rows idx=0, esc=0)

#define CTX_BSTRIDE  400       // bytes per ctx/W row (384 fp8 + 16 pad)

// ---- smem layout (bytes) ----
#define OFF_W      0
#define SZ_W       (D * CTX_BSTRIDE)              // 51200
#define OFF_CTX    (OFF_W + SZ_W)                 // 51200
#define SZ_CTX     (TILE_N * CTX_BSTRIDE)         // 25600
#define OFF_IDX    (OFF_CTX + SZ_CTX)             // 76800 : 3*256*4 = 3072
#define OFF_AV     (OFF_IDX + 3072)               // 512
#define OFF_SP     (OFF_AV + 512)                 // 64*8*4 = 2048
#define OFF_ESC    (OFF_SP + 2048)                // 256
#define OFF_CODEP  (OFF_ESC + 256)                // 128*2*4 = 1024
#define OFF_CODES  (OFF_CODEP + 1024)             // 512
#define OFF_ZS     (OFF_CODES + 512)              // 1536
#define OFF_EP     (OFF_ZS + 1536)                // 64
#define SMEM_BYTES (OFF_EP + 64)                  // 85248

// W pre-converted to e4m3, row stride 400 B
__device__ __align__(16) unsigned char g_Wf8[SZ_W];

__device__ __forceinline__ uint32_t pack4_e4m3(float4 v) {
    uint16_t lo, hi;
    asm("cvt.rn.satfinite.e4m3x2.f32 %0, %1, %2;" : "=h"(lo) : "f"(v.y), "f"(v.x));
    asm("cvt.rn.satfinite.e4m3x2.f32 %0, %1, %2;" : "=h"(hi) : "f"(v.w), "f"(v.z));
    return (uint32_t)lo | ((uint32_t)hi << 16);
}

__global__ void prep_w_kernel(const float* __restrict__ W) {
    int i = blockIdx.x * 256 + threadIdx.x;      // 0..12287 (128 rows x 96 quads)
    int d = i / 96, j = i % 96;
    float4 v = ((const float4*)W)[i];
    *(uint32_t*)(g_Wf8 + d * CTX_BSTRIDE + j * 4) = pack4_e4m3(v);
}

__device__ __forceinline__ float fast_tanhf(float x) {
    float y; asm("tanh.approx.f32 %0, %1;" : "=f"(y) : "f"(x)); return y;
}
__device__ __forceinline__ void mma_f8(float* acc, uint32_t a0, uint32_t a1,
                                       uint32_t a2, uint32_t a3,
                                       uint32_t b0, uint32_t b1) {
    asm volatile(
        "mma.sync.aligned.m16n8k32.row.col.f32.e4m3.e4m3.f32 "
        "{%0,%1,%2,%3},{%4,%5,%6,%7},{%8,%9},{%0,%1,%2,%3};"
        : "+f"(acc[0]), "+f"(acc[1]), "+f"(acc[2]), "+f"(acc[3])
        : "r"(a0), "r"(a1), "r"(a2), "r"(a3), "r"(b0), "r"(b1));
}
__device__ __forceinline__ void ldsm_x4(uint32_t& r0, uint32_t& r1,
                                        uint32_t& r2, uint32_t& r3, uint32_t saddr) {
    asm volatile("ldmatrix.sync.aligned.m8n8.x4.shared.b16 {%0,%1,%2,%3}, [%4];"
                 : "=r"(r0), "=r"(r1), "=r"(r2), "=r"(r3) : "r"(saddr));
}
__device__ __forceinline__ float4 ldg_nc_v4(const float* p) {
    float4 r;
    asm volatile("ld.global.nc.v4.f32 {%0,%1,%2,%3}, [%4];"
                 : "=f"(r.x), "=f"(r.y), "=f"(r.z), "=f"(r.w) : "l"(p));
    return r;
}

__global__ void __launch_bounds__(THREADS, 2)
acv_fused_kernel(const int* __restrict__ xs_xt,
                 const int* __restrict__ path_idx,
                 const float* __restrict__ value_vocab,
                 const float* __restrict__ path_vocab,
                 const float* __restrict__ att_vec,
                 const float* __restrict__ dense_w,
                 const float* __restrict__ dense_b,
                 float* __restrict__ out)
{
    extern __shared__ unsigned char smem[];
    int*   sxi   = (int*)(smem + OFF_IDX);
    int*   pxi   = sxi + 256;
    int*   txi   = pxi + 256;
    float* avs   = (float*)(smem + OFF_AV);
    float* sp    = (float*)(smem + OFF_SP);
    float* esc   = (float*)(smem + OFF_ESC);
    float* codep = (float*)(smem + OFF_CODEP);
    float* codes = (float*)(smem + OFF_CODES);
    float* zs    = (float*)(smem + OFF_ZS);
    float* ep    = (float*)(smem + OFF_EP);

    const int tid  = threadIdx.x;
    const int b    = blockIdx.x;
    const int lane = tid & 31;
    const int warp = tid >> 5;

    // ---- cp.async W (pre-converted fp8) into smem ----
    {
        uint32_t ws = (uint32_t)__cvta_generic_to_shared(smem + OFF_W);
        const char* wg = (const char*)g_Wf8;
        for (int i = tid; i < SZ_W / 16; i += THREADS)
            asm volatile("cp.async.cg.shared.global [%0], [%1], 16;"
                         :: "r"(ws + i * 16), "l"(wg + i * 16));
        asm volatile("cp.async.commit_group;");
    }

    // ---- stage indices (padded to 256) ----
    for (int i = tid; i < 2 * NCTX; i += THREADS) {
        int v = xs_xt[b * 2 * NCTX + i];
        if (i & 1) txi[i >> 1] = v; else sxi[i >> 1] = v;
    }
    if (tid < NCTX) pxi[tid] = path_idx[b * NCTX + tid];
    if (tid < 56) { sxi[NCTX + tid] = 0; pxi[NCTX + tid] = 0; txi[NCTX + tid] = 0; }
    if (tid < D) avs[tid] = att_vec[tid];
    asm volatile("cp.async.wait_group 0;");
    __syncthreads();

    // ---- warp tiling: 2 m-warps (32 rows) x 8 n-warps (16 cols), m32n16 per warp ----
    const int mwarp = warp & 1;
    const int nwarp = warp >> 1;
    const int g  = lane >> 2;
    const int tg = lane & 3;

    const uint32_t ctx_s = (uint32_t)__cvta_generic_to_shared(smem + OFF_CTX);
    const uint32_t w_s   = (uint32_t)__cvta_generic_to_shared(smem + OFF_W);

    const uint32_t a_off0 = (uint32_t)((mwarp * 32 + (lane & 15)) * CTX_BSTRIDE + (lane >> 4) * 16);
    const uint32_t a_off1 = a_off0 + 16 * CTX_BSTRIDE;
    const int bc = ((lane >> 4) << 3) + (lane & 7);
    const uint32_t b_off = (uint32_t)((nwarp * 16 + bc) * CTX_BSTRIDE + ((lane >> 3) & 1) * 16);

    // per-thread columns: col = nwarp*16 + jj*8 + tg*2 + c2  (jj in 0..1)
    float av4[4];
#pragma unroll
    for (int jj = 0; jj < 2; jj++) {
        int col = nwarp * 16 + jj * 8 + tg * 2;
        av4[jj * 2]     = avs[col];
        av4[jj * 2 + 1] = avs[col + 1];
    }

    float cpart[4] = {0.f, 0.f, 0.f, 0.f};
    float resum = 0.f;

    for (int t = 0; t < NTILES; t++) {
        const int n0 = t * TILE_N;

        // ---- gather tile t: 64 rows x 96 quads / 512 thr = 12 quads, batches of 4 ----
        for (int s = 0; s < 12; s += 4) {
            float4 v[4]; int soff[4];
#pragma unroll
            for (int u = 0; u < 4; u++) {
                int i = tid + (s + u) * THREADS;
                int r = i / 96, q = i - r * 96;
                int seg = q >> 5, j = q & 31;
                int idx = (seg == 0) ? sxi[n0 + r] : (seg == 1) ? pxi[n0 + r] : txi[n0 + r];
                const float* tab = (seg == 1) ? path_vocab : value_vocab;
                v[u] = ldg_nc_v4(tab + (size_t)idx * 128 + j * 4);
                soff[u] = r * CTX_BSTRIDE + q * 4;
            }
#pragma unroll
            for (int u = 0; u < 4; u++)
                *(uint32_t*)(smem + OFF_CTX + soff[u]) = pack4_e4m3(v[u]);
        }
        __syncthreads();

        // ---- GEMM: acc[m][jj][c], 12 k32-steps ----
        float acc[2][2][4];
#pragma unroll
        for (int m = 0; m < 2; m++)
#pragma unroll
            for (int jj = 0; jj < 2; jj++)
#pragma unroll
                for (int c = 0; c < 4; c++) acc[m][jj][c] = 0.f;

#pragma unroll
        for (int kk = 0; kk < 12; kk++) {
            uint32_t a[2][4], bq[4];
            ldsm_x4(a[0][0], a[0][1], a[0][2], a[0][3], ctx_s + a_off0 + kk * 32);
            ldsm_x4(a[1][0], a[1][1], a[1][2], a[1][3], ctx_s + a_off1 + kk * 32);
            ldsm_x4(bq[0], bq[1], bq[2], bq[3], w_s + b_off + kk * 32);
#pragma unroll
            for (int m = 0; m < 2; m++) {
                mma_f8(acc[m][0], a[m][0], a[m][1], a[m][2], a[m][3], bq[0], bq[1]);
                mma_f8(acc[m][1], a[m][0], a[m][1], a[m][2], a[m][3], bq[2], bq[3]);
            }
        }

        // ---- tanh in place + score partials ----
#pragma unroll
        for (int m = 0; m < 2; m++)
#pragma unroll
            for (int jj = 0; jj < 2; jj++)
#pragma unroll
                for (int c = 0; c < 4; c++)
                    acc[m][jj][c] = fast_tanhf(acc[m][jj][c]);

#pragma unroll
        for (int m = 0; m < 2; m++) {
#pragma unroll
            for (int h = 0; h < 2; h++) {
                float p = 0.f;
#pragma unroll
                for (int jj = 0; jj < 2; jj++) {
                    p += av4[jj * 2]     * acc[m][jj][h * 2];
                    p += av4[jj * 2 + 1] * acc[m][jj][h * 2 + 1];
                }
                p += __shfl_xor_sync(0xFFFFFFFFu, p, 1);
                p += __shfl_xor_sync(0xFFFFFFFFu, p, 2);
                if (tg == 0) {
                    int row = mwarp * 32 + m * 16 + h * 8 + g;
                    sp[row * 8 + nwarp] = p;
                }
            }
        }
        __syncthreads();

        if (tid < TILE_N) {
            float s = 0.f;
#pragma unroll
            for (int w8 = 0; w8 < 8; w8++) s += sp[tid * 8 + w8];
            float e = (n0 + tid < NCTX) ? __expf(s) : 0.f;
            esc[tid] = e;
            resum += e;
        }
        __syncthreads();

        // ---- weighted accumulation from registers ----
#pragma unroll
        for (int m = 0; m < 2; m++) {
#pragma unroll
            for (int h = 0; h < 2; h++) {
                float e = esc[mwarp * 32 + m * 16 + h * 8 + g];
#pragma unroll
                for (int jj = 0; jj < 2; jj++) {
                    cpart[jj * 2]     += e * acc[m][jj][h * 2];
                    cpart[jj * 2 + 1] += e * acc[m][jj][h * 2 + 1];
                }
            }
        }
        // next gather may overwrite ctx: all warps passed GEMM (sp-sync above).
    }

    // ---- reduce cpart across g, write per-mwarp col partials ----
#pragma unroll
    for (int off = 4; off < 32; off <<= 1)
#pragma unroll
        for (int i = 0; i < 4; i++)
            cpart[i] += __shfl_xor_sync(0xFFFFFFFFu, cpart[i], off);
    if (g == 0) {
#pragma unroll
        for (int jj = 0; jj < 2; jj++) {
            int col = nwarp * 16 + jj * 8 + tg * 2;
            codep[col * 2 + mwarp]       = cpart[jj * 2];
            codep[(col + 1) * 2 + mwarp] = cpart[jj * 2 + 1];
        }
    }
    if (tid < TILE_N) {
        float s = resum;
#pragma unroll
        for (int off = 16; off > 0; off >>= 1)
            s += __shfl_xor_sync(0xFFFFFFFFu, s, off);
        if (lane == 0) ep[warp] = s;
    }
    __syncthreads();

    float esum = ep[0] + ep[1];
    if (tid < D) {
        float c = codep[tid * 2] + codep[tid * 2 + 1];
        codes[tid] = c / esum;
    }
    __syncthreads();

    // ---- dense + sigmoid ----
    {
        const int grp = tid >> 7, dcol = tid & 127;
        float z = 0.f;
#pragma unroll 8
        for (int d2 = 0; d2 < 32; d2++) {
            int d = grp * 32 + d2;
            z += codes[d] * dense_w[d * OUTD + dcol];
        }
        if (grp != 0) zs[(grp - 1) * 128 + dcol] = z;
        __syncthreads();
        if (grp == 0) {
            float zz = z + zs[dcol] + zs[128 + dcol] + zs[256 + dcol] + dense_b[dcol];
            out[b * OUTD + dcol] = 1.f / (1.f + __expf(-zz));
        }
    }
}

extern "C" void kernel_launch(void* const* d_in, const int* in_sizes, int n_in,
                              void* d_out, int out_size)
{
    const int*   xs_xt       = (const int*)d_in[0];
    const int*   path_idx    = (const int*)d_in[1];
    const float* value_vocab = (const float*)d_in[2];
    const float* path_vocab  = (const float*)d_in[3];
    const float* W           = (const float*)d_in[4];
    const float* att_vec     = (const float*)d_in[5];
    const float* dense_w     = (const float*)d_in[6];
    const float* dense_b     = (const float*)d_in[7];
    float*       out         = (float*)d_out;

    prep_w_kernel<<<48, 256>>>(W);

    cudaFuncSetAttribute(acv_fused_kernel,
                         cudaFuncAttributeMaxDynamicSharedMemorySize, SMEM_BYTES);
    acv_fused_kernel<<<1024, THREADS, SMEM_BYTES>>>(
        xs_xt, path_idx, value_vocab, path_vocab, att_vec,
        dense_w, dense_b, out);
}

// round 9
// speedup vs baseline: 3.6002x; 1.1003x over previous
#include <cuda_runtime.h>
#include <cuda_bf16.h>
#include <stdint.h>

// Problem constants
#define VALUE_VOCAB 100000
#define NCTX      200
#define D         128
#define F         384
#define OUTD      128
#define THREADS   512
#define TILE_N    64
#define NTILES    4            // 4 x 64 = 256 rows (padded; invalid rows esc=0)

#define CTX_BSTRIDE  400       // bytes per ctx/W row (384 fp8 + 16 pad)

// ---- smem layout (bytes) ----
#define OFF_W      0
#define SZ_W       (D * CTX_BSTRIDE)              // 51200
#define OFF_CTX    (OFF_W + SZ_W)                 // 51200
#define SZ_CTX     (TILE_N * CTX_BSTRIDE)         // 25600
#define OFF_PTR    (OFF_CTX + SZ_CTX)             // 76800 : 3*256*8 = 6144
#define OFF_AV     (OFF_PTR + 6144)               // 512
#define OFF_SP     (OFF_AV + 512)                 // 64*8*4 = 2048
#define OFF_ESC    (OFF_SP + 2048)                // 256
#define OFF_CODEP  (OFF_ESC + 256)                // 1024
#define OFF_CODES  (OFF_CODEP + 1024)             // 512
#define OFF_ZS     (OFF_CODES + 512)              // 1536
#define OFF_EP     (OFF_ZS + 1536)                // 64
#define SMEM_BYTES (OFF_EP + 64)                  // ~88.6 KB (2 CTAs/SM)

// W pre-converted to e4m3, row stride 400 B
__device__ __align__(16) unsigned char g_Wf8[SZ_W];
// value_vocab pre-converted to e4m3, rows of 128 B
__device__ __align__(16) unsigned char g_valf8[(size_t)VALUE_VOCAB * 128];

__device__ __forceinline__ uint32_t pack4_e4m3(float4 v) {
    uint16_t lo, hi;
    asm("cvt.rn.satfinite.e4m3x2.f32 %0, %1, %2;" : "=h"(lo) : "f"(v.y), "f"(v.x));
    asm("cvt.rn.satfinite.e4m3x2.f32 %0, %1, %2;" : "=h"(hi) : "f"(v.w), "f"(v.z));
    return (uint32_t)lo | ((uint32_t)hi << 16);
}

__global__ void prep_w_kernel(const float* __restrict__ W) {
    int i = blockIdx.x * 256 + threadIdx.x;      // 0..12287 (128 rows x 96 quads)
    int d = i / 96, j = i % 96;
    float4 v = ((const float4*)W)[i];
    *(uint32_t*)(g_Wf8 + d * CTX_BSTRIDE + j * 4) = pack4_e4m3(v);
}

// value_vocab fp32 -> fp8: 100000*32 = 3.2M quads; each thread does 4 consecutive
__global__ void prep_val_kernel(const float* __restrict__ vv) {
    size_t q0 = ((size_t)blockIdx.x * 256 + threadIdx.x) * 4;
    uint32_t o[4];
#pragma unroll
    for (int u = 0; u < 4; u++)
        o[u] = pack4_e4m3(((const float4*)vv)[q0 + u]);
    *(uint4*)(g_valf8 + q0 * 4) = make_uint4(o[0], o[1], o[2], o[3]);
}

__device__ __forceinline__ float fast_tanhf(float x) {
    float y; asm("tanh.approx.f32 %0, %1;" : "=f"(y) : "f"(x)); return y;
}
__device__ __forceinline__ void mma_f8(float* acc, uint32_t a0, uint32_t a1,
                                       uint32_t a2, uint32_t a3,
                                       uint32_t b0, uint32_t b1) {
    asm volatile(
        "mma.sync.aligned.m16n8k32.row.col.f32.e4m3.e4m3.f32 "
        "{%0,%1,%2,%3},{%4,%5,%6,%7},{%8,%9},{%0,%1,%2,%3};"
        : "+f"(acc[0]), "+f"(acc[1]), "+f"(acc[2]), "+f"(acc[3])
        : "r"(a0), "r"(a1), "r"(a2), "r"(a3), "r"(b0), "r"(b1));
}
__device__ __forceinline__ void ldsm_x4(uint32_t& r0, uint32_t& r1,
                                        uint32_t& r2, uint32_t& r3, uint32_t saddr) {
    asm volatile("ldmatrix.sync.aligned.m8n8.x4.shared.b16 {%0,%1,%2,%3}, [%4];"
                 : "=r"(r0), "=r"(r1), "=r"(r2), "=r"(r3) : "r"(saddr));
}
__device__ __forceinline__ float4 ldg_nc_v4(const float* p) {
    float4 r;
    asm volatile("ld.global.nc.v4.f32 {%0,%1,%2,%3}, [%4];"
                 : "=f"(r.x), "=f"(r.y), "=f"(r.z), "=f"(r.w) : "l"(p));
    return r;
}
__device__ __forceinline__ uint4 ldg_nc_u4(const void* p) {
    uint4 r;
    asm volatile("ld.global.nc.v4.b32 {%0,%1,%2,%3}, [%4];"
                 : "=r"(r.x), "=r"(r.y), "=r"(r.z), "=r"(r.w) : "l"(p));
    return r;
}

__global__ void __launch_bounds__(THREADS, 2)
acv_fused_kernel(const int* __restrict__ xs_xt,
                 const int* __restrict__ path_idx,
                 const float* __restrict__ path_vocab,
                 const float* __restrict__ att_vec,
                 const float* __restrict__ dense_w,
                 const float* __restrict__ dense_b,
                 float* __restrict__ out)
{
    extern __shared__ unsigned char smem[];
    uint64_t* vsp = (uint64_t*)(smem + OFF_PTR);         // xs value-row ptrs
    uint64_t* vpp = vsp + 256;                           // path row ptrs
    uint64_t* vtp = vpp + 256;                           // xt value-row ptrs
    float* avs   = (float*)(smem + OFF_AV);
    float* sp    = (float*)(smem + OFF_SP);
    float* esc   = (float*)(smem + OFF_ESC);
    float* codep = (float*)(smem + OFF_CODEP);
    float* codes = (float*)(smem + OFF_CODES);
    float* zs    = (float*)(smem + OFF_ZS);
    float* ep    = (float*)(smem + OFF_EP);

    const int tid  = threadIdx.x;
    const int b    = blockIdx.x;
    const int lane = tid & 31;
    const int warp = tid >> 5;

    // ---- cp.async W (pre-converted fp8) into smem ----
    {
        uint32_t ws = (uint32_t)__cvta_generic_to_shared(smem + OFF_W);
        const char* wg = (const char*)g_Wf8;
        for (int i = tid; i < SZ_W / 16; i += THREADS)
            asm volatile("cp.async.cg.shared.global [%0], [%1], 16;"
                         :: "r"(ws + i * 16), "l"(wg + i * 16));
        asm volatile("cp.async.commit_group;");
    }

    // ---- stage row pointers (padded to 256 rows) ----
    for (int i = tid; i < 2 * NCTX; i += THREADS) {
        int v = xs_xt[b * 2 * NCTX + i];
        uint64_t p = (uint64_t)(g_valf8 + (size_t)v * 128);
        if (i & 1) vtp[i >> 1] = p; else vsp[i >> 1] = p;
    }
    if (tid < NCTX)
        vpp[tid] = (uint64_t)(path_vocab + (size_t)path_idx[b * NCTX + tid] * 128);
    if (tid < 56) {
        vsp[NCTX + tid] = (uint64_t)g_valf8;
        vpp[NCTX + tid] = (uint64_t)path_vocab;
        vtp[NCTX + tid] = (uint64_t)g_valf8;
    }
    if (tid < D) avs[tid] = att_vec[tid];
    asm volatile("cp.async.wait_group 0;");
    __syncthreads();

    // ---- warp tiling: 2 m-warps (32 rows) x 8 n-warps (16 cols), m32n16 per warp ----
    const int mwarp = warp & 1;
    const int nwarp = warp >> 1;
    const int g  = lane >> 2;
    const int tg = lane & 3;

    const uint32_t ctx_s = (uint32_t)__cvta_generic_to_shared(smem + OFF_CTX);
    const uint32_t w_s   = (uint32_t)__cvta_generic_to_shared(smem + OFF_W);

    const uint32_t a_off0 = (uint32_t)((mwarp * 32 + (lane & 15)) * CTX_BSTRIDE + (lane >> 4) * 16);
    const uint32_t a_off1 = a_off0 + 16 * CTX_BSTRIDE;
    const int bc = ((lane >> 4) << 3) + (lane & 7);
    const uint32_t b_off = (uint32_t)((nwarp * 16 + bc) * CTX_BSTRIDE + ((lane >> 3) & 1) * 16);

    float av4[4];
#pragma unroll
    for (int jj = 0; jj < 2; jj++) {
        int col = nwarp * 16 + jj * 8 + tg * 2;
        av4[jj * 2]     = avs[col];
        av4[jj * 2 + 1] = avs[col + 1];
    }

    // gather role: 8 threads per row
    const int grow = tid >> 3;     // row within tile (0..63)
    const int gsub = tid & 7;

    float cpart[4] = {0.f, 0.f, 0.f, 0.f};
    float resum = 0.f;

    for (int t = 0; t < NTILES; t++) {
        const int n0 = t * TILE_N;

        // ---- gather tile t: per thread = 1 row, 1/8 of its 3 segments ----
        {
            const int gr = n0 + grow;
            const char* ps = (const char*)vsp[gr];
            const char* pp = (const char*)vpp[gr];
            const char* pt = (const char*)vtp[gr];
            // fp8 straight copies (xs, xt)
            uint4 vx = ldg_nc_u4(ps + gsub * 16);
            uint4 vt2 = ldg_nc_u4(pt + gsub * 16);
            // path fp32 -> fp8 (4 quads, lane-interleaved for coalescing)
            float4 f0 = ldg_nc_v4((const float*)pp + (gsub)      * 4);
            float4 f1 = ldg_nc_v4((const float*)pp + (gsub + 8)  * 4);
            float4 f2 = ldg_nc_v4((const float*)pp + (gsub + 16) * 4);
            float4 f3 = ldg_nc_v4((const float*)pp + (gsub + 24) * 4);
            unsigned char* crow = smem + OFF_CTX + grow * CTX_BSTRIDE;
            *(uint4*)(crow + gsub * 16)       = vx;
            *(uint4*)(crow + 256 + gsub * 16) = vt2;
            *(uint32_t*)(crow + 128 + (gsub)      * 4) = pack4_e4m3(f0);
            *(uint32_t*)(crow + 128 + (gsub + 8)  * 4) = pack4_e4m3(f1);
            *(uint32_t*)(crow + 128 + (gsub + 16) * 4) = pack4_e4m3(f2);
            *(uint32_t*)(crow + 128 + (gsub + 24) * 4) = pack4_e4m3(f3);
        }
        __syncthreads();

        // ---- GEMM: acc[m][jj][c], 12 k32-steps ----
        float acc[2][2][4];
#pragma unroll
        for (int m = 0; m < 2; m++)
#pragma unroll
            for (int jj = 0; jj < 2; jj++)
#pragma unroll
                for (int c = 0; c < 4; c++) acc[m][jj][c] = 0.f;

#pragma unroll
        for (int kk = 0; kk < 12; kk++) {
            uint32_t a[2][4], bq[4];
            ldsm_x4(a[0][0], a[0][1], a[0][2], a[0][3], ctx_s + a_off0 + kk * 32);
            ldsm_x4(a[1][0], a[1][1], a[1][2], a[1][3], ctx_s + a_off1 + kk * 32);
            ldsm_x4(bq[0], bq[1], bq[2], bq[3], w_s + b_off + kk * 32);
#pragma unroll
            for (int m = 0; m < 2; m++) {
                mma_f8(acc[m][0], a[m][0], a[m][1], a[m][2], a[m][3], bq[0], bq[1]);
                mma_f8(acc[m][1], a[m][0], a[m][1], a[m][2], a[m][3], bq[2], bq[3]);
            }
        }

        // ---- tanh in place + score partials ----
#pragma unroll
        for (int m = 0; m < 2; m++)
#pragma unroll
            for (int jj = 0; jj < 2; jj++)
#pragma unroll
                for (int c = 0; c < 4; c++)
                    acc[m][jj][c] = fast_tanhf(acc[m][jj][c]);

#pragma unroll
        for (int m = 0; m < 2; m++) {
#pragma unroll
            for (int h = 0; h < 2; h++) {
                float p = 0.f;
#pragma unroll
                for (int jj = 0; jj < 2; jj++) {
                    p += av4[jj * 2]     * acc[m][jj][h * 2];
                    p += av4[jj * 2 + 1] * acc[m][jj][h * 2 + 1];
                }
                p += __shfl_xor_sync(0xFFFFFFFFu, p, 1);
                p += __shfl_xor_sync(0xFFFFFFFFu, p, 2);
                if (tg == 0) {
                    int row = mwarp * 32 + m * 16 + h * 8 + g;
                    sp[row * 8 + nwarp] = p;
                }
            }
        }
        __syncthreads();

        if (tid < TILE_N) {
            float s = 0.f;
#pragma unroll
            for (int w8 = 0; w8 < 8; w8++) s += sp[tid * 8 + w8];
            float e = (n0 + tid < NCTX) ? __expf(s) : 0.f;
            esc[tid] = e;
            resum += e;
        }
        __syncthreads();

        // ---- weighted accumulation from registers ----
#pragma unroll
        for (int m = 0; m < 2; m++) {
#pragma unroll
            for (int h = 0; h < 2; h++) {
                float e = esc[mwarp * 32 + m * 16 + h * 8 + g];
#pragma unroll
                for (int jj = 0; jj < 2; jj++) {
                    cpart[jj * 2]     += e * acc[m][jj][h * 2];
                    cpart[jj * 2 + 1] += e * acc[m][jj][h * 2 + 1];
                }
            }
        }
        // next gather may overwrite ctx: all warps passed GEMM (sp-sync above).
    }

    // ---- reduce cpart across g, write per-mwarp col partials ----
#pragma unroll
    for (int off = 4; off < 32; off <<= 1)
#pragma unroll
        for (int i = 0; i < 4; i++)
            cpart[i] += __shfl_xor_sync(0xFFFFFFFFu, cpart[i], off);
    if (g == 0) {
#pragma unroll
        for (int jj = 0; jj < 2; jj++) {
            int col = nwarp * 16 + jj * 8 + tg * 2;
            codep[col * 2 + mwarp]       = cpart[jj * 2];
            codep[(col + 1) * 2 + mwarp] = cpart[jj * 2 + 1];
        }
    }
    if (tid < TILE_N) {
        float s = resum;
#pragma unroll
        for (int off = 16; off > 0; off >>= 1)
            s += __shfl_xor_sync(0xFFFFFFFFu, s, off);
        if (lane == 0) ep[warp] = s;
    }
    __syncthreads();

    float esum = ep[0] + ep[1];
    if (tid < D) {
        float c = codep[tid * 2] + codep[tid * 2 + 1];
        codes[tid] = c / esum;
    }
    __syncthreads();

    // ---- dense + sigmoid ----
    {
        const int grp = tid >> 7, dcol = tid & 127;
        float z = 0.f;
#pragma unroll 8
        for (int d2 = 0; d2 < 32; d2++) {
            int d = grp * 32 + d2;
            z += codes[d] * dense_w[d * OUTD + dcol];
        }
        if (grp != 0) zs[(grp - 1) * 128 + dcol] = z;
        __syncthreads();
        if (grp == 0) {
            float zz = z + zs[dcol] + zs[128 + dcol] + zs[256 + dcol] + dense_b[dcol];
            out[b * OUTD + dcol] = 1.f / (1.f + __expf(-zz));
        }
    }
}

extern "C" void kernel_launch(void* const* d_in, const int* in_sizes, int n_in,
                              void* d_out, int out_size)
{
    const int*   xs_xt       = (const int*)d_in[0];
    const int*   path_idx    = (const int*)d_in[1];
    const float* value_vocab = (const float*)d_in[2];
    const float* path_vocab  = (const float*)d_in[3];
    const float* W           = (const float*)d_in[4];
    const float* att_vec     = (const float*)d_in[5];
    const float* dense_w     = (const float*)d_in[6];
    const float* dense_b     = (const float*)d_in[7];
    float*       out         = (float*)d_out;

    prep_w_kernel<<<48, 256>>>(W);
    prep_val_kernel<<<3125, 256>>>(value_vocab);   // 3125*256*4 = 3.2M quads exactly

    cudaFuncSetAttribute(acv_fused_kernel,
                         cudaFuncAttributeMaxDynamicSharedMemorySize, SMEM_BYTES);
    acv_fused_kernel<<<1024, THREADS, SMEM_BYTES>>>(
        xs_xt, path_idx, path_vocab, att_vec,
        dense_w, dense_b, out);
}